// round 1
// baseline (speedup 1.0000x reference)
#include <cuda_runtime.h>
#include <cuda_bf16.h>
#include <math.h>

#define L_ 128
#define B_ 512
#define D_ 512
#define S_ 128
#define NROWS (L_*B_)   // 65536

// ---- device scratch (static: no allocation allowed) ----
__device__ float g_W[D_*S_];                 // W[d][s] = means[s][d]/var[d]
__device__ float g_A[S_*S_];                 // row-stochastic transition matrix
__device__ float g_mm[S_];                   // sum_d means^2/var
__device__ float g_ivar[D_];
__device__ float g_scal[1];                  // ldc
__device__ float g_xx[NROWS];                // sum_d x^2/var per (t,b)
__device__ float g_dens[(size_t)NROWS*S_];   // xm - 0.5*mm  (33.5 MB)
__device__ float g_rowobj[B_];

// ============================ prep kernels ============================

__global__ void prep_var_kernel(const float* __restrict__ var){
    __shared__ float sred[512];
    int t = threadIdx.x;                      // 512 threads
    float v = var[t];
    g_ivar[t] = 1.0f / v;
    sred[t] = logf(v);
    __syncthreads();
    for (int o = 256; o > 0; o >>= 1){
        if (t < o) sred[t] += sred[t + o];
        __syncthreads();
    }
    if (t == 0)
        g_scal[0] = -(float)(D_/2) * logf(2.0f * 3.14159265358979323846f) - 0.5f * sred[0];
}

__global__ void prep_A_kernel(const float* __restrict__ tp){
    __shared__ float sred[128];
    int s = blockIdx.x, t = threadIdx.x;      // 128 blocks x 128 threads
    float v = tp[s*S_ + t];
    sred[t] = v; __syncthreads();
    for (int o = 64; o > 0; o >>= 1){
        if (t < o) sred[t] = fmaxf(sred[t], sred[t+o]);
        __syncthreads();
    }
    float mx = sred[0]; __syncthreads();
    float e = expf(v - mx);
    sred[t] = e; __syncthreads();
    for (int o = 64; o > 0; o >>= 1){
        if (t < o) sred[t] += sred[t+o];
        __syncthreads();
    }
    g_A[s*S_ + t] = e / sred[0];
}

__global__ void prep_W_kernel(const float* __restrict__ means){
    __shared__ float sred[128];
    int s = blockIdx.x, t = threadIdx.x;      // 128 x 128
    float acc = 0.0f;
    for (int d = t; d < D_; d += 128){
        float m = means[s*D_ + d];
        float w = m * g_ivar[d];
        g_W[d*S_ + s] = w;
        acc += m * w;
    }
    sred[t] = acc; __syncthreads();
    for (int o = 64; o > 0; o >>= 1){
        if (t < o) sred[t] += sred[t+o];
        __syncthreads();
    }
    if (t == 0) g_mm[s] = sred[0];
}

// xx[row] = sum_d x^2 * ivar ; one warp per row
__global__ void __launch_bounds__(256) xx_kernel(const float* __restrict__ X){
    int warp = threadIdx.x >> 5, lane = threadIdx.x & 31;
    int row = blockIdx.x * 8 + warp;
    const float4* xp = (const float4*)(X + (size_t)row * D_);
    const float4* iv = (const float4*)g_ivar;
    float acc = 0.0f;
    #pragma unroll
    for (int c = 0; c < 4; c++){
        float4 v = xp[c*32 + lane];
        float4 w = iv[c*32 + lane];
        acc += v.x*v.x*w.x + v.y*v.y*w.y + v.z*v.z*w.z + v.w*v.w*w.w;
    }
    #pragma unroll
    for (int o = 16; o > 0; o >>= 1) acc += __shfl_xor_sync(0xffffffffu, acc, o);
    if (lane == 0) g_xx[row] = acc;
}

// ============================ phase 1: GEMM ============================
// dens[n][s] = sum_d X[n][d]*W[d][s] - 0.5*mm[s]
// 128x128 tile, BK=16, 256 threads, 8x8 microtile
__global__ void __launch_bounds__(256) gemm_kernel(const float* __restrict__ X){
    __shared__ float As[16][128];
    __shared__ float Bs[16][128];
    const int tid = threadIdx.x;
    const int m0 = blockIdx.x * 128;
    const int tx = tid & 15, ty = tid >> 4;
    float acc[8][8];
    #pragma unroll
    for (int i = 0; i < 8; i++)
        #pragma unroll
        for (int j = 0; j < 8; j++) acc[i][j] = 0.0f;

    for (int k0 = 0; k0 < D_; k0 += 16){
        #pragma unroll
        for (int i = 0; i < 2; i++){
            int f4 = tid + i*256;             // 0..511
            int row = f4 >> 2;                // 0..127
            int kq  = f4 & 3;                 // 0..3
            float4 v = *(const float4*)(X + (size_t)(m0+row)*D_ + k0 + kq*4);
            As[kq*4+0][row] = v.x; As[kq*4+1][row] = v.y;
            As[kq*4+2][row] = v.z; As[kq*4+3][row] = v.w;
        }
        #pragma unroll
        for (int i = 0; i < 2; i++){
            int f4 = tid + i*256;
            int kr = f4 >> 5;                 // 0..15
            int c4 = f4 & 31;                 // 0..31
            *(float4*)(&Bs[kr][c4*4]) = *(const float4*)(g_W + (size_t)(k0+kr)*S_ + c4*4);
        }
        __syncthreads();
        #pragma unroll
        for (int kk = 0; kk < 16; kk++){
            float a[8], b[8];
            float4 a0 = *(const float4*)(&As[kk][ty*8]);
            float4 a1 = *(const float4*)(&As[kk][ty*8+4]);
            a[0]=a0.x; a[1]=a0.y; a[2]=a0.z; a[3]=a0.w;
            a[4]=a1.x; a[5]=a1.y; a[6]=a1.z; a[7]=a1.w;
            float4 b0 = *(const float4*)(&Bs[kk][tx*8]);
            float4 b1 = *(const float4*)(&Bs[kk][tx*8+4]);
            b[0]=b0.x; b[1]=b0.y; b[2]=b0.z; b[3]=b0.w;
            b[4]=b1.x; b[5]=b1.y; b[6]=b1.z; b[7]=b1.w;
            #pragma unroll
            for (int i = 0; i < 8; i++)
                #pragma unroll
                for (int j = 0; j < 8; j++)
                    acc[i][j] += a[i]*b[j];
        }
        __syncthreads();
    }
    float mmv[8];
    #pragma unroll
    for (int j = 0; j < 8; j++) mmv[j] = 0.5f * g_mm[tx*8 + j];
    #pragma unroll
    for (int i = 0; i < 8; i++){
        float4 o0, o1;
        o0.x = acc[i][0]-mmv[0]; o0.y = acc[i][1]-mmv[1];
        o0.z = acc[i][2]-mmv[2]; o0.w = acc[i][3]-mmv[3];
        o1.x = acc[i][4]-mmv[4]; o1.y = acc[i][5]-mmv[5];
        o1.z = acc[i][6]-mmv[6]; o1.w = acc[i][7]-mmv[7];
        float* dst = g_dens + (size_t)(m0 + ty*8 + i)*S_ + tx*8;
        *(float4*)(dst)     = o0;
        *(float4*)(dst + 4) = o1;
    }
}

// ============================ phase 2: recursion ============================

__device__ __forceinline__ float warpmax_(float x){
    #pragma unroll
    for (int o = 16; o > 0; o >>= 1) x = fmaxf(x, __shfl_xor_sync(0xffffffffu, x, o));
    return x;
}
__device__ __forceinline__ float warpsum_(float x){
    #pragma unroll
    for (int o = 16; o > 0; o >>= 1) x += __shfl_xor_sync(0xffffffffu, x, o);
    return x;
}
// 4-row block max over 128 threads (4 warps)
__device__ __forceinline__ void rowmax4(const float (&v)[4], float (&out)[4],
                                        float* sred, int lane, int warp){
    #pragma unroll
    for (int r = 0; r < 4; r++){
        float x = warpmax_(v[r]);
        if (lane == 0) sred[r*4 + warp] = x;
    }
    __syncthreads();
    #pragma unroll
    for (int r = 0; r < 4; r++)
        out[r] = fmaxf(fmaxf(sred[r*4+0], sred[r*4+1]), fmaxf(sred[r*4+2], sred[r*4+3]));
    __syncthreads();
}
__device__ __forceinline__ void rowsum4(const float (&v)[4], float (&out)[4],
                                        float* sred, int lane, int warp){
    #pragma unroll
    for (int r = 0; r < 4; r++){
        float x = warpsum_(v[r]);
        if (lane == 0) sred[r*4 + warp] = x;
    }
    __syncthreads();
    #pragma unroll
    for (int r = 0; r < 4; r++)
        out[r] = (sred[r*4+0] + sred[r*4+1]) + (sred[r*4+2] + sred[r*4+3]);
    __syncthreads();
}
__device__ __forceinline__ float blockmax1(float x, float* sred, int lane, int warp){
    x = warpmax_(x);
    if (lane == 0) sred[warp] = x;
    __syncthreads();
    float r = fmaxf(fmaxf(sred[0], sred[1]), fmaxf(sred[2], sred[3]));
    __syncthreads();
    return r;
}

#define FWD_SMEM_FLOATS (S_*S_ + 4*S_ + 16 + 4)
#define FWD_SMEM_BYTES  (FWD_SMEM_FLOATS * 4)

__global__ void __launch_bounds__(128) forward_kernel(const float* __restrict__ masks){
    extern __shared__ float sm[];
    float* sA   = sm;                         // 16384
    float* sa   = sm + S_*S_;                 // 4*128 scaled probs
    float* sred = sa + 4*S_;                  // 16
    float* sls  = sred + 16;                  // 4 log-scales
    const int tid = threadIdx.x, lane = tid & 31, warp = tid >> 5;
    const int b0 = blockIdx.x * 4;

    for (int i = tid; i < S_*S_; i += 128) sA[i] = g_A[i];
    const float ldc = g_scal[0];
    const float log_pi = -4.852030263919617f; // -log(128)

    // t = 0
    float dl[4], dmax[4];
    #pragma unroll
    for (int r = 0; r < 4; r++)
        dl[r] = g_dens[(size_t)(b0+r)*S_ + tid] + (ldc - 0.5f*g_xx[b0+r]);
    rowmax4(dl, dmax, sred, lane, warp);
    #pragma unroll
    for (int r = 0; r < 4; r++) sa[r*S_ + tid] = __expf(dl[r] - dmax[r]);
    if (tid == 0){
        sls[0] = log_pi + dmax[0]; sls[1] = log_pi + dmax[1];
        sls[2] = log_pi + dmax[2]; sls[3] = log_pi + dmax[3];
    }
    __syncthreads();

    for (int t = 1; t < L_; t++){
        float mk[4], w[4];
        #pragma unroll
        for (int r = 0; r < 4; r++){
            int bb = t*B_ + b0 + r;
            dl[r] = g_dens[(size_t)bb*S_ + tid] + (ldc - 0.5f*g_xx[bb]);
            mk[r] = masks[bb];
        }
        rowmax4(dl, dmax, sred, lane, warp);
        #pragma unroll
        for (int r = 0; r < 4; r++) w[r] = __expf(dl[r] - dmax[r]);

        // matv: y[r] = sum_s a[r][s] * A[s][tid]
        float y0 = 0.f, y1 = 0.f, y2 = 0.f, y3 = 0.f;
        #pragma unroll 8
        for (int s4 = 0; s4 < 32; s4++){
            float4 a0v = *(const float4*)(sa + 0*S_ + s4*4);
            float4 a1v = *(const float4*)(sa + 1*S_ + s4*4);
            float4 a2v = *(const float4*)(sa + 2*S_ + s4*4);
            float4 a3v = *(const float4*)(sa + 3*S_ + s4*4);
            float A0 = sA[(s4*4+0)*S_ + tid];
            y0 += a0v.x*A0; y1 += a1v.x*A0; y2 += a2v.x*A0; y3 += a3v.x*A0;
            float A1 = sA[(s4*4+1)*S_ + tid];
            y0 += a0v.y*A1; y1 += a1v.y*A1; y2 += a2v.y*A1; y3 += a3v.y*A1;
            float A2 = sA[(s4*4+2)*S_ + tid];
            y0 += a0v.z*A2; y1 += a1v.z*A2; y2 += a2v.z*A2; y3 += a3v.z*A2;
            float A3 = sA[(s4*4+3)*S_ + tid];
            y0 += a0v.w*A3; y1 += a1v.w*A3; y2 += a2v.w*A3; y3 += a3v.w*A3;
        }
        float y[4] = { y0*w[0], y1*w[1], y2*w[2], y3*w[3] };
        float ymax[4];
        rowmax4(y, ymax, sred, lane, warp);

        float vnew[4], lsn[4];
        #pragma unroll
        for (int r = 0; r < 4; r++){
            float lsold = sls[r];
            float m = mk[r];
            if (m == 1.0f){
                vnew[r] = y[r] / ymax[r];
                lsn[r]  = lsold + dmax[r] + __logf(ymax[r]);
            } else if (m == 0.0f){
                vnew[r] = sa[r*S_ + tid];
                lsn[r]  = lsold;
            } else {
                // exact log-domain blend (block-uniform branch)
                float bl = m * (lsold + dmax[r] + __logf(fmaxf(y[r], 1e-37f)))
                         + (1.0f - m) * (lsold + __logf(fmaxf(sa[r*S_ + tid], 1e-37f)));
                float bmax = blockmax1(bl, sred, lane, warp);
                vnew[r] = __expf(bl - bmax);
                lsn[r]  = bmax;
            }
        }
        __syncthreads();
        #pragma unroll
        for (int r = 0; r < 4; r++) sa[r*S_ + tid] = vnew[r];
        if (tid == 0){
            sls[0] = lsn[0]; sls[1] = lsn[1]; sls[2] = lsn[2]; sls[3] = lsn[3];
        }
        __syncthreads();
    }

    // objective per row: ls + log(sum_s a)
    float sv[4], ssum[4];
    #pragma unroll
    for (int r = 0; r < 4; r++) sv[r] = sa[r*S_ + tid];
    rowsum4(sv, ssum, sred, lane, warp);
    if (tid == 0){
        #pragma unroll
        for (int r = 0; r < 4; r++)
            g_rowobj[b0 + r] = sls[r] + __logf(ssum[r]);
    }
}

// deterministic final reduction
__global__ void finalize_kernel(float* __restrict__ out, int out_size){
    __shared__ float sred[512];
    int t = threadIdx.x;
    sred[t] = g_rowobj[t];
    __syncthreads();
    for (int o = 256; o > 0; o >>= 1){
        if (t < o) sred[t] += sred[t+o];
        __syncthreads();
    }
    for (int i = t; i < out_size; i += 512)
        out[i] = (i == 0) ? sred[0] : 0.0f;
}

// ============================ launch ============================

extern "C" void kernel_launch(void* const* d_in, const int* in_sizes, int n_in,
                              void* d_out, int out_size){
    const float* sents   = (const float*)d_in[0];  // (L,B,D)
    const float* masks   = (const float*)d_in[1];  // (L,B)
    const float* tparams = (const float*)d_in[2];  // (S,S)
    const float* means   = (const float*)d_in[3];  // (S,D)
    const float* var     = (const float*)d_in[4];  // (D,)

    cudaFuncSetAttribute(forward_kernel,
                         cudaFuncAttributeMaxDynamicSharedMemorySize, FWD_SMEM_BYTES);

    prep_var_kernel<<<1, 512>>>(var);
    prep_A_kernel<<<S_, 128>>>(tparams);
    prep_W_kernel<<<S_, 128>>>(means);
    xx_kernel<<<NROWS/8, 256>>>(sents);
    gemm_kernel<<<NROWS/128, 256>>>(sents);
    forward_kernel<<<B_/4, 128, FWD_SMEM_BYTES>>>(masks);
    finalize_kernel<<<1, 512>>>((float*)d_out, out_size);
}

// round 3
// speedup vs baseline: 1.5733x; 1.5733x over previous
#include <cuda_runtime.h>
#include <cuda_bf16.h>
#include <math.h>

typedef unsigned int u32;

#define L_ 128
#define B_ 512
#define D_ 512
#define S_ 128
#define NROWS (L_*B_)

// ---- device scratch (static: no allocation allowed) ----
__device__ __nv_bfloat16 g_Wbf[S_*D_];       // Wt[s][d] = means[s][d]/var[d] (bf16)
__device__ float g_A[S_*S_];                 // row-stochastic transition matrix
__device__ float g_mm[S_];                   // sum_d means^2/var
__device__ float g_ivar[D_];
__device__ float g_scal[1];                  // ldc
__device__ float g_dens[(size_t)NROWS*S_];   // FULL log-density (33.5 MB)
__device__ float g_rowobj[B_];

// ============================ prep kernels ============================

__global__ void prep_var_kernel(const float* __restrict__ var){
    __shared__ float sred[512];
    int t = threadIdx.x;
    float v = var[t];
    g_ivar[t] = 1.0f / v;
    sred[t] = logf(v);
    __syncthreads();
    for (int o = 256; o > 0; o >>= 1){
        if (t < o) sred[t] += sred[t + o];
        __syncthreads();
    }
    if (t == 0){
        g_scal[0] = -(float)(D_/2) * logf(2.0f * 3.14159265358979323846f) - 0.5f * sred[0];
    }
}

__global__ void prep_A_kernel(const float* __restrict__ tp){
    __shared__ float sred[128];
    int s = blockIdx.x;
    int t = threadIdx.x;
    float v = tp[s*S_ + t];
    sred[t] = v;
    __syncthreads();
    for (int o = 64; o > 0; o >>= 1){
        if (t < o) sred[t] = fmaxf(sred[t], sred[t+o]);
        __syncthreads();
    }
    float mx = sred[0];
    __syncthreads();
    float e = expf(v - mx);
    sred[t] = e;
    __syncthreads();
    for (int o = 64; o > 0; o >>= 1){
        if (t < o) sred[t] += sred[t+o];
        __syncthreads();
    }
    g_A[s*S_ + t] = e / sred[0];
}

__global__ void prep_W_kernel(const float* __restrict__ means){
    __shared__ float sred[128];
    int s = blockIdx.x;
    int t = threadIdx.x;
    float acc = 0.0f;
    for (int d = t; d < D_; d += 128){
        float m = means[s*D_ + d];
        float w = m * g_ivar[d];
        g_Wbf[s*D_ + d] = __float2bfloat16(w);
        acc += m * w;
    }
    sred[t] = acc;
    __syncthreads();
    for (int o = 64; o > 0; o >>= 1){
        if (t < o) sred[t] += sred[t+o];
        __syncthreads();
    }
    if (t == 0) g_mm[s] = sred[0];
}

// ============================ phase 1: tensor-core GEMM ============================
// dens[n][s] = sum_d X[n][d]*Wt[s][d] + ldc - 0.5*mm[s] - 0.5*xx[n]

__device__ __forceinline__ u32 swz(u32 off){
    return off ^ ((off >> 3) & 0x70u);
}

__device__ __forceinline__ void ldsm_x4(u32* r, u32 saddr){
    asm volatile("ldmatrix.sync.aligned.m8n8.x4.shared.b16 {%0,%1,%2,%3}, [%4];"
        : "=r"(r[0]), "=r"(r[1]), "=r"(r[2]), "=r"(r[3]) : "r"(saddr));
}

__device__ __forceinline__ void mma_bf16(float* c, const u32* a, u32 b0, u32 b1){
    asm volatile("mma.sync.aligned.m16n8k16.row.col.f32.bf16.bf16.f32 "
        "{%0,%1,%2,%3}, {%4,%5,%6,%7}, {%8,%9}, {%0,%1,%2,%3};"
        : "+f"(c[0]), "+f"(c[1]), "+f"(c[2]), "+f"(c[3])
        : "r"(a[0]), "r"(a[1]), "r"(a[2]), "r"(a[3]), "r"(b0), "r"(b1));
}

__global__ void __launch_bounds__(256) gemm_kernel(const float* __restrict__ X){
    __shared__ __align__(128) unsigned char smA[128*128];
    __shared__ __align__(128) unsigned char smB[128*128];
    __shared__ float sxx[128][16];
    __shared__ float sxxr[128];

    const int tid  = threadIdx.x;
    const int lane = tid & 31;
    const int warp = tid >> 5;
    const int warp_m = (warp >> 1) * 32;
    const int warp_n = (warp & 1) * 64;
    const size_t m0 = (size_t)blockIdx.x * 128;

    const u32 aBase = (u32)__cvta_generic_to_shared(smA);
    const u32 bBase = (u32)__cvta_generic_to_shared(smB);

    float acc[2][8][4];
    #pragma unroll
    for (int t = 0; t < 2; t++){
        #pragma unroll
        for (int j = 0; j < 8; j++){
            #pragma unroll
            for (int c = 0; c < 4; c++){ acc[t][j][c] = 0.0f; }
        }
    }
    float xacc[8];
    #pragma unroll
    for (int i = 0; i < 8; i++){ xacc[i] = 0.0f; }

    const int arow0 = tid >> 4;   // + i*16 -> 8 rows per thread
    const int acol4 = tid & 15;   // float4 column within 64
    const int brow0 = tid >> 3;   // + i*32 -> 4 rows per thread
    const int bchk  = tid & 7;    // 16B chunk within 128B row

    for (int kt = 0; kt < 8; kt++){
        const int k0 = kt * 64;
        float4 iv = *(const float4*)(g_ivar + k0 + acol4*4);
        #pragma unroll
        for (int i = 0; i < 8; i++){
            int r = arow0 + i*16;
            float4 v = *(const float4*)(X + (m0 + r)*D_ + k0 + acol4*4);
            xacc[i] += v.x*v.x*iv.x + v.y*v.y*iv.y + v.z*v.z*iv.z + v.w*v.w*iv.w;
            __nv_bfloat162 p0 = __floats2bfloat162_rn(v.x, v.y);
            __nv_bfloat162 p1 = __floats2bfloat162_rn(v.z, v.w);
            uint2 pk;
            pk.x = *(u32*)&p0;
            pk.y = *(u32*)&p1;
            u32 off = (u32)(r*128 + acol4*8);
            *(uint2*)(smA + swz(off)) = pk;
        }
        #pragma unroll
        for (int i = 0; i < 4; i++){
            int r = brow0 + i*32;
            uint4 v = *(const uint4*)((const unsigned char*)g_Wbf + (size_t)r*(D_*2) + k0*2 + bchk*16);
            u32 off = (u32)(r*128 + bchk*16);
            *(uint4*)(smB + swz(off)) = v;
        }
        __syncthreads();
        #pragma unroll
        for (int kk = 0; kk < 4; kk++){
            u32 af[2][4];
            #pragma unroll
            for (int t = 0; t < 2; t++){
                u32 row = (u32)(warp_m + t*16 + (lane & 15));
                u32 off = row*128u + (u32)(kk*32) + (u32)((lane >> 4)*16);
                ldsm_x4(af[t], aBase + swz(off));
            }
            u32 bf[4][4];
            #pragma unroll
            for (int g = 0; g < 4; g++){
                u32 row = (u32)(warp_n + g*16 + (lane >> 4)*8 + (lane & 7));
                u32 off = row*128u + (u32)(kk*32) + (u32)(((lane >> 3) & 1)*16);
                ldsm_x4(bf[g], bBase + swz(off));
            }
            #pragma unroll
            for (int t = 0; t < 2; t++){
                #pragma unroll
                for (int g = 0; g < 4; g++){
                    mma_bf16(acc[t][g*2+0], af[t], bf[g][0], bf[g][1]);
                    mma_bf16(acc[t][g*2+1], af[t], bf[g][2], bf[g][3]);
                }
            }
        }
        __syncthreads();
    }

    // reduce per-row xx (16 column-partials per row)
    #pragma unroll
    for (int i = 0; i < 8; i++){ sxx[arow0 + i*16][acol4] = xacc[i]; }
    __syncthreads();
    if (tid < 128){
        float s = 0.0f;
        #pragma unroll
        for (int c = 0; c < 16; c++){ s += sxx[tid][c]; }
        sxxr[tid] = s;
    }
    __syncthreads();

    const float ldc = g_scal[0];
    #pragma unroll
    for (int t = 0; t < 2; t++){
        int rl = warp_m + t*16 + (lane >> 2);
        float bias0 = ldc - 0.5f * sxxr[rl];
        float bias1 = ldc - 0.5f * sxxr[rl + 8];
        #pragma unroll
        for (int j = 0; j < 8; j++){
            int n = warp_n + j*8 + (lane & 3)*2;
            float mm0 = 0.5f * g_mm[n];
            float mm1 = 0.5f * g_mm[n+1];
            float2 o0;
            float2 o1;
            o0.x = acc[t][j][0] - mm0 + bias0;
            o0.y = acc[t][j][1] - mm1 + bias0;
            o1.x = acc[t][j][2] - mm0 + bias1;
            o1.y = acc[t][j][3] - mm1 + bias1;
            *(float2*)(g_dens + (m0 + rl)*S_ + n)     = o0;
            *(float2*)(g_dens + (m0 + rl + 8)*S_ + n) = o1;
        }
    }
}

// ============================ phase 2: recursion ============================

__device__ __forceinline__ float warpmax_(float x){
    #pragma unroll
    for (int o = 16; o > 0; o >>= 1){ x = fmaxf(x, __shfl_xor_sync(0xffffffffu, x, o)); }
    return x;
}
__device__ __forceinline__ float warpsum_(float x){
    #pragma unroll
    for (int o = 16; o > 0; o >>= 1){ x += __shfl_xor_sync(0xffffffffu, x, o); }
    return x;
}
__device__ __forceinline__ void rowmax4(const float* v, float* out,
                                        float* sred, int lane, int warp){
    #pragma unroll
    for (int r = 0; r < 4; r++){
        float x = warpmax_(v[r]);
        if (lane == 0) sred[r*4 + warp] = x;
    }
    __syncthreads();
    #pragma unroll
    for (int r = 0; r < 4; r++){
        out[r] = fmaxf(fmaxf(sred[r*4+0], sred[r*4+1]), fmaxf(sred[r*4+2], sred[r*4+3]));
    }
    __syncthreads();
}
__device__ __forceinline__ void rowsum4(const float* v, float* out,
                                        float* sred, int lane, int warp){
    #pragma unroll
    for (int r = 0; r < 4; r++){
        float x = warpsum_(v[r]);
        if (lane == 0) sred[r*4 + warp] = x;
    }
    __syncthreads();
    #pragma unroll
    for (int r = 0; r < 4; r++){
        out[r] = (sred[r*4+0] + sred[r*4+1]) + (sred[r*4+2] + sred[r*4+3]);
    }
    __syncthreads();
}
__device__ __forceinline__ float blockmax1(float x, float* sred, int lane, int warp){
    x = warpmax_(x);
    if (lane == 0) sred[warp] = x;
    __syncthreads();
    float r = fmaxf(fmaxf(sred[0], sred[1]), fmaxf(sred[2], sred[3]));
    __syncthreads();
    return r;
}

#define FWD_SMEM_FLOATS (S_*S_ + 4*S_ + 16 + 4)
#define FWD_SMEM_BYTES  (FWD_SMEM_FLOATS * 4)

__global__ void __launch_bounds__(128) forward_kernel(const float* __restrict__ masks){
    extern __shared__ float sm[];
    float* sA   = sm;
    float* sa   = sm + S_*S_;
    float* sred = sa + 4*S_;
    float* sls  = sred + 16;
    const int tid = threadIdx.x;
    const int lane = tid & 31;
    const int warp = tid >> 5;
    const int b0 = blockIdx.x * 4;

    for (int i = tid; i < S_*S_; i += 128){ sA[i] = g_A[i]; }
    const float log_pi = -4.852030263919617f; // -log(128)

    float dl[4];
    float dmax[4];
    #pragma unroll
    for (int r = 0; r < 4; r++){
        dl[r] = g_dens[(size_t)(b0+r)*S_ + tid];
    }
    rowmax4(dl, dmax, sred, lane, warp);
    #pragma unroll
    for (int r = 0; r < 4; r++){ sa[r*S_ + tid] = __expf(dl[r] - dmax[r]); }
    if (tid == 0){
        sls[0] = log_pi + dmax[0];
        sls[1] = log_pi + dmax[1];
        sls[2] = log_pi + dmax[2];
        sls[3] = log_pi + dmax[3];
    }
    __syncthreads();

    for (int t = 1; t < L_; t++){
        float mk[4];
        float w[4];
        #pragma unroll
        for (int r = 0; r < 4; r++){
            int bb = t*B_ + b0 + r;
            dl[r] = g_dens[(size_t)bb*S_ + tid];
            mk[r] = masks[bb];
        }
        rowmax4(dl, dmax, sred, lane, warp);
        #pragma unroll
        for (int r = 0; r < 4; r++){ w[r] = __expf(dl[r] - dmax[r]); }

        float y0 = 0.f;
        float y1 = 0.f;
        float y2 = 0.f;
        float y3 = 0.f;
        #pragma unroll 8
        for (int s4 = 0; s4 < 32; s4++){
            float4 a0v = *(const float4*)(sa + 0*S_ + s4*4);
            float4 a1v = *(const float4*)(sa + 1*S_ + s4*4);
            float4 a2v = *(const float4*)(sa + 2*S_ + s4*4);
            float4 a3v = *(const float4*)(sa + 3*S_ + s4*4);
            float A0 = sA[(s4*4+0)*S_ + tid];
            y0 += a0v.x*A0; y1 += a1v.x*A0; y2 += a2v.x*A0; y3 += a3v.x*A0;
            float A1 = sA[(s4*4+1)*S_ + tid];
            y0 += a0v.y*A1; y1 += a1v.y*A1; y2 += a2v.y*A1; y3 += a3v.y*A1;
            float A2 = sA[(s4*4+2)*S_ + tid];
            y0 += a0v.z*A2; y1 += a1v.z*A2; y2 += a2v.z*A2; y3 += a3v.z*A2;
            float A3 = sA[(s4*4+3)*S_ + tid];
            y0 += a0v.w*A3; y1 += a1v.w*A3; y2 += a2v.w*A3; y3 += a3v.w*A3;
        }
        float y[4];
        y[0] = y0*w[0];
        y[1] = y1*w[1];
        y[2] = y2*w[2];
        y[3] = y3*w[3];
        float ymax[4];
        rowmax4(y, ymax, sred, lane, warp);

        float vnew[4];
        float lsn[4];
        #pragma unroll
        for (int r = 0; r < 4; r++){
            float lsold = sls[r];
            float m = mk[r];
            if (m == 1.0f){
                vnew[r] = y[r] / ymax[r];
                lsn[r]  = lsold + dmax[r] + __logf(ymax[r]);
            } else if (m == 0.0f){
                vnew[r] = sa[r*S_ + tid];
                lsn[r]  = lsold;
            } else {
                float bl = m * (lsold + dmax[r] + __logf(fmaxf(y[r], 1e-37f)))
                         + (1.0f - m) * (lsold + __logf(fmaxf(sa[r*S_ + tid], 1e-37f)));
                float bmax = blockmax1(bl, sred, lane, warp);
                vnew[r] = __expf(bl - bmax);
                lsn[r]  = bmax;
            }
        }
        __syncthreads();
        #pragma unroll
        for (int r = 0; r < 4; r++){ sa[r*S_ + tid] = vnew[r]; }
        if (tid == 0){
            sls[0] = lsn[0];
            sls[1] = lsn[1];
            sls[2] = lsn[2];
            sls[3] = lsn[3];
        }
        __syncthreads();
    }

    float sv[4];
    float ssum[4];
    #pragma unroll
    for (int r = 0; r < 4; r++){ sv[r] = sa[r*S_ + tid]; }
    rowsum4(sv, ssum, sred, lane, warp);
    if (tid == 0){
        #pragma unroll
        for (int r = 0; r < 4; r++){
            g_rowobj[b0 + r] = sls[r] + __logf(ssum[r]);
        }
    }
}

// deterministic final reduction
__global__ void finalize_kernel(float* __restrict__ out, int out_size){
    __shared__ float sred[512];
    int t = threadIdx.x;
    sred[t] = g_rowobj[t];
    __syncthreads();
    for (int o = 256; o > 0; o >>= 1){
        if (t < o) sred[t] += sred[t+o];
        __syncthreads();
    }
    for (int i = t; i < out_size; i += 512){
        out[i] = (i == 0) ? sred[0] : 0.0f;
    }
}

// ============================ launch ============================

extern "C" void kernel_launch(void* const* d_in, const int* in_sizes, int n_in,
                              void* d_out, int out_size){
    const float* sents   = (const float*)d_in[0];  // (L,B,D)
    const float* masks   = (const float*)d_in[1];  // (L,B)
    const float* tparams = (const float*)d_in[2];  // (S,S)
    const float* means   = (const float*)d_in[3];  // (S,D)
    const float* var     = (const float*)d_in[4];  // (D,)

    (void)tparams;
    cudaFuncSetAttribute(forward_kernel,
                         cudaFuncAttributeMaxDynamicSharedMemorySize, FWD_SMEM_BYTES);

    prep_var_kernel<<<1, 512>>>(var);
    prep_A_kernel<<<S_, 128>>>(d_in[2] ? (const float*)d_in[2] : tparams);
    prep_W_kernel<<<S_, 128>>>(means);
    gemm_kernel<<<NROWS/128, 256>>>(sents);
    forward_kernel<<<B_/4, 128, FWD_SMEM_BYTES>>>(masks);
    finalize_kernel<<<1, 512>>>((float*)d_out, out_size);
}

// round 4
// speedup vs baseline: 2.1046x; 1.3377x over previous
#include <cuda_runtime.h>
#include <cuda_bf16.h>
#include <math.h>

typedef unsigned int u32;

#define L_ 128
#define B_ 512
#define D_ 512
#define S_ 128
#define NROWS (L_*B_)

// ---- device scratch (static: no allocation allowed) ----
__device__ __nv_bfloat16 g_Wbf[S_*D_];       // Wt[s][d] = means[s][d]/var[d] (bf16)
__device__ float g_A[S_*S_];                 // row-stochastic transition matrix
__device__ float g_mm[S_];                   // sum_d means^2/var
__device__ float g_ivar[D_];
__device__ float g_scal[1];                  // ldc
__device__ float g_dens[(size_t)NROWS*S_];   // FULL log-density (33.5 MB)
__device__ float g_rowobj[B_];

// ============================ prep kernels ============================

__global__ void prep_var_kernel(const float* __restrict__ var){
    __shared__ float sred[512];
    int t = threadIdx.x;
    float v = var[t];
    g_ivar[t] = 1.0f / v;
    sred[t] = logf(v);
    __syncthreads();
    for (int o = 256; o > 0; o >>= 1){
        if (t < o) sred[t] += sred[t + o];
        __syncthreads();
    }
    if (t == 0){
        g_scal[0] = -(float)(D_/2) * logf(2.0f * 3.14159265358979323846f) - 0.5f * sred[0];
    }
}

__global__ void prep_A_kernel(const float* __restrict__ tp){
    __shared__ float sred[128];
    int s = blockIdx.x;
    int t = threadIdx.x;
    float v = tp[s*S_ + t];
    sred[t] = v;
    __syncthreads();
    for (int o = 64; o > 0; o >>= 1){
        if (t < o) sred[t] = fmaxf(sred[t], sred[t+o]);
        __syncthreads();
    }
    float mx = sred[0];
    __syncthreads();
    float e = expf(v - mx);
    sred[t] = e;
    __syncthreads();
    for (int o = 64; o > 0; o >>= 1){
        if (t < o) sred[t] += sred[t+o];
        __syncthreads();
    }
    g_A[s*S_ + t] = e / sred[0];
}

__global__ void prep_W_kernel(const float* __restrict__ means){
    __shared__ float sred[128];
    int s = blockIdx.x;
    int t = threadIdx.x;
    float acc = 0.0f;
    for (int d = t; d < D_; d += 128){
        float m = means[s*D_ + d];
        float w = m * g_ivar[d];
        g_Wbf[s*D_ + d] = __float2bfloat16(w);
        acc += m * w;
    }
    sred[t] = acc;
    __syncthreads();
    for (int o = 64; o > 0; o >>= 1){
        if (t < o) sred[t] += sred[t+o];
        __syncthreads();
    }
    if (t == 0) g_mm[s] = sred[0];
}

// ============================ phase 1: tensor-core GEMM ============================
// dens[n][s] = sum_d X[n][d]*Wt[s][d] + ldc - 0.5*mm[s] - 0.5*xx[n]

__device__ __forceinline__ u32 swz(u32 off){
    return off ^ ((off >> 3) & 0x70u);
}

__device__ __forceinline__ void ldsm_x4(u32* r, u32 saddr){
    asm volatile("ldmatrix.sync.aligned.m8n8.x4.shared.b16 {%0,%1,%2,%3}, [%4];"
        : "=r"(r[0]), "=r"(r[1]), "=r"(r[2]), "=r"(r[3]) : "r"(saddr));
}

__device__ __forceinline__ void mma_bf16(float* c, const u32* a, u32 b0, u32 b1){
    asm volatile("mma.sync.aligned.m16n8k16.row.col.f32.bf16.bf16.f32 "
        "{%0,%1,%2,%3}, {%4,%5,%6,%7}, {%8,%9}, {%0,%1,%2,%3};"
        : "+f"(c[0]), "+f"(c[1]), "+f"(c[2]), "+f"(c[3])
        : "r"(a[0]), "r"(a[1]), "r"(a[2]), "r"(a[3]), "r"(b0), "r"(b1));
}

__global__ void __launch_bounds__(256) gemm_kernel(const float* __restrict__ X){
    __shared__ __align__(128) unsigned char smA[128*128];
    __shared__ __align__(128) unsigned char smB[128*128];
    __shared__ float sxx[128][16];
    __shared__ float sxxr[128];

    const int tid  = threadIdx.x;
    const int lane = tid & 31;
    const int warp = tid >> 5;
    const int warp_m = (warp >> 1) * 32;
    const int warp_n = (warp & 1) * 64;
    const size_t m0 = (size_t)blockIdx.x * 128;

    const u32 aBase = (u32)__cvta_generic_to_shared(smA);
    const u32 bBase = (u32)__cvta_generic_to_shared(smB);

    float acc[2][8][4];
    #pragma unroll
    for (int t = 0; t < 2; t++){
        #pragma unroll
        for (int j = 0; j < 8; j++){
            #pragma unroll
            for (int c = 0; c < 4; c++){ acc[t][j][c] = 0.0f; }
        }
    }
    float xacc[8];
    #pragma unroll
    for (int i = 0; i < 8; i++){ xacc[i] = 0.0f; }

    const int arow0 = tid >> 4;   // + i*16 -> 8 rows per thread
    const int acol4 = tid & 15;   // float4 column within 64
    const int brow0 = tid >> 3;   // + i*32 -> 4 rows per thread
    const int bchk  = tid & 7;    // 16B chunk within 128B row

    // register prefetch buffers
    float4 xr[8];
    uint4  br[4];
    float4 ivr;

    // initial load (kt = 0)
    {
        const int k0 = 0;
        ivr = *(const float4*)(g_ivar + k0 + acol4*4);
        #pragma unroll
        for (int i = 0; i < 8; i++){
            xr[i] = *(const float4*)(X + (m0 + arow0 + i*16)*D_ + k0 + acol4*4);
        }
        #pragma unroll
        for (int i = 0; i < 4; i++){
            br[i] = *(const uint4*)((const unsigned char*)g_Wbf + (size_t)(brow0 + i*32)*(D_*2) + k0*2 + bchk*16);
        }
    }

    for (int kt = 0; kt < 8; kt++){
        // store stage: regs -> smem (+ xx accumulate)
        #pragma unroll
        for (int i = 0; i < 8; i++){
            int r = arow0 + i*16;
            float4 v = xr[i];
            xacc[i] += v.x*v.x*ivr.x + v.y*v.y*ivr.y + v.z*v.z*ivr.z + v.w*v.w*ivr.w;
            __nv_bfloat162 p0 = __floats2bfloat162_rn(v.x, v.y);
            __nv_bfloat162 p1 = __floats2bfloat162_rn(v.z, v.w);
            uint2 pk;
            pk.x = *(u32*)&p0;
            pk.y = *(u32*)&p1;
            u32 off = (u32)(r*128 + acol4*8);
            *(uint2*)(smA + swz(off)) = pk;
        }
        #pragma unroll
        for (int i = 0; i < 4; i++){
            int r = brow0 + i*32;
            u32 off = (u32)(r*128 + bchk*16);
            *(uint4*)(smB + swz(off)) = br[i];
        }
        __syncthreads();

        // prefetch next tile while MMAs run
        if (kt < 7){
            const int k0 = (kt + 1) * 64;
            ivr = *(const float4*)(g_ivar + k0 + acol4*4);
            #pragma unroll
            for (int i = 0; i < 8; i++){
                xr[i] = *(const float4*)(X + (m0 + arow0 + i*16)*D_ + k0 + acol4*4);
            }
            #pragma unroll
            for (int i = 0; i < 4; i++){
                br[i] = *(const uint4*)((const unsigned char*)g_Wbf + (size_t)(brow0 + i*32)*(D_*2) + k0*2 + bchk*16);
            }
        }

        #pragma unroll
        for (int kk = 0; kk < 4; kk++){
            u32 af[2][4];
            #pragma unroll
            for (int t = 0; t < 2; t++){
                u32 row = (u32)(warp_m + t*16 + (lane & 15));
                u32 off = row*128u + (u32)(kk*32) + (u32)((lane >> 4)*16);
                ldsm_x4(af[t], aBase + swz(off));
            }
            u32 bf[4][4];
            #pragma unroll
            for (int g = 0; g < 4; g++){
                u32 row = (u32)(warp_n + g*16 + (lane >> 4)*8 + (lane & 7));
                u32 off = row*128u + (u32)(kk*32) + (u32)(((lane >> 3) & 1)*16);
                ldsm_x4(bf[g], bBase + swz(off));
            }
            #pragma unroll
            for (int t = 0; t < 2; t++){
                #pragma unroll
                for (int g = 0; g < 4; g++){
                    mma_bf16(acc[t][g*2+0], af[t], bf[g][0], bf[g][1]);
                    mma_bf16(acc[t][g*2+1], af[t], bf[g][2], bf[g][3]);
                }
            }
        }
        __syncthreads();
    }

    // reduce per-row xx (16 column-partials per row)
    #pragma unroll
    for (int i = 0; i < 8; i++){ sxx[arow0 + i*16][acol4] = xacc[i]; }
    __syncthreads();
    if (tid < 128){
        float s = 0.0f;
        #pragma unroll
        for (int c = 0; c < 16; c++){ s += sxx[tid][c]; }
        sxxr[tid] = s;
    }
    __syncthreads();

    const float ldc = g_scal[0];
    #pragma unroll
    for (int t = 0; t < 2; t++){
        int rl = warp_m + t*16 + (lane >> 2);
        float bias0 = ldc - 0.5f * sxxr[rl];
        float bias1 = ldc - 0.5f * sxxr[rl + 8];
        #pragma unroll
        for (int j = 0; j < 8; j++){
            int n = warp_n + j*8 + (lane & 3)*2;
            float mm0 = 0.5f * g_mm[n];
            float mm1 = 0.5f * g_mm[n+1];
            float2 o0;
            float2 o1;
            o0.x = acc[t][j][0] - mm0 + bias0;
            o0.y = acc[t][j][1] - mm1 + bias0;
            o1.x = acc[t][j][2] - mm0 + bias1;
            o1.y = acc[t][j][3] - mm1 + bias1;
            *(float2*)(g_dens + (m0 + rl)*S_ + n)     = o0;
            *(float2*)(g_dens + (m0 + rl + 8)*S_ + n) = o1;
        }
    }
}

// ============================ phase 2: recursion (v2) ============================
// 256 threads: n = tid&127 (state), g = tid>>7 (row group: rows 2g, 2g+1).
// Warps 0-3 handle rows 0,1; warps 4-7 handle rows 2,3.

__device__ __forceinline__ float warpmax_(float x){
    #pragma unroll
    for (int o = 16; o > 0; o >>= 1){ x = fmaxf(x, __shfl_xor_sync(0xffffffffu, x, o)); }
    return x;
}
__device__ __forceinline__ float warpsum_(float x){
    #pragma unroll
    for (int o = 16; o > 0; o >>= 1){ x += __shfl_xor_sync(0xffffffffu, x, o); }
    return x;
}
__device__ __forceinline__ float max4s(const float* p){
    return fmaxf(fmaxf(p[0], p[1]), fmaxf(p[2], p[3]));
}
__device__ __forceinline__ float sum4s(const float* p){
    return (p[0] + p[1]) + (p[2] + p[3]);
}

#define FWD_SMEM_FLOATS (S_*S_ + 4*S_ + 16 + 16 + 4)
#define FWD_SMEM_BYTES  (FWD_SMEM_FLOATS * 4)

__global__ void __launch_bounds__(256) forward_kernel(const float* __restrict__ masks){
    extern __shared__ float sm[];
    float* sA    = sm;                 // 16384: A[s][n]
    float* sa    = sm + S_*S_;         // 512: 4 rows of scaled probs
    float* sredA = sa + 4*S_;          // 16
    float* sredB = sredA + 16;         // 16
    float* sls   = sredB + 16;         // 4 log-scales

    const int tid  = threadIdx.x;
    const int lane = tid & 31;
    const int warp = tid >> 5;
    const int n    = tid & 127;
    const int g    = tid >> 7;          // 0 or 1
    const int wl   = warp & 3;          // warp index within group
    const int r0   = 2*g;
    const int r1   = 2*g + 1;
    const int b0   = blockIdx.x * 4;

    for (int i = tid; i < S_*S_; i += 256){ sA[i] = g_A[i]; }
    const float log_pi = -4.852030263919617f; // -log(128)

    // ---- t = 0 ----
    {
        float dla = g_dens[(size_t)(b0 + r0)*S_ + n];
        float dlb = g_dens[(size_t)(b0 + r1)*S_ + n];
        float wda = warpmax_(dla);
        float wdb = warpmax_(dlb);
        if (lane == 0){ sredA[r0*4 + wl] = wda; sredA[r1*4 + wl] = wdb; }
        __syncthreads();
        float dmaxa = max4s(sredA + r0*4);
        float dmaxb = max4s(sredA + r1*4);
        sa[r0*S_ + n] = __expf(dla - dmaxa);
        sa[r1*S_ + n] = __expf(dlb - dmaxb);
        if (tid == 0 || tid == 128){
            sls[r0] = log_pi + dmaxa;
            sls[r1] = log_pi + dmaxb;
        }
        __syncthreads();
    }

    for (int t = 1; t < L_; t++){
        // early loads (consumed after the matv -> latency hidden)
        int bb0 = t*B_ + b0 + r0;
        float dla = g_dens[(size_t)bb0*S_ + n];
        float dlb = g_dens[(size_t)(bb0+1)*S_ + n];
        float mka = masks[bb0];
        float mkb = masks[bb0 + 1];
        float aolda = sa[r0*S_ + n];
        float aoldb = sa[r1*S_ + n];

        // matv: y[h][n] = sum_s a[2g+h][s] * A[s][n]
        float y0 = 0.0f;
        float y1 = 0.0f;
        const float* saA = sa + r0*S_;
        const float* saB = sa + r1*S_;
        #pragma unroll 8
        for (int s4 = 0; s4 < 32; s4++){
            float4 av = *(const float4*)(saA + s4*4);
            float4 bv = *(const float4*)(saB + s4*4);
            float A0 = sA[(s4*4+0)*S_ + n];
            y0 += av.x*A0; y1 += bv.x*A0;
            float A1 = sA[(s4*4+1)*S_ + n];
            y0 += av.y*A1; y1 += bv.y*A1;
            float A2 = sA[(s4*4+2)*S_ + n];
            y0 += av.z*A2; y1 += bv.z*A2;
            float A3 = sA[(s4*4+3)*S_ + n];
            y0 += av.w*A3; y1 += bv.w*A3;
        }

        // dmax reduction
        float wda = warpmax_(dla);
        float wdb = warpmax_(dlb);
        if (lane == 0){ sredA[r0*4 + wl] = wda; sredA[r1*4 + wl] = wdb; }
        __syncthreads();                       // S1
        float dmaxa = max4s(sredA + r0*4);
        float dmaxb = max4s(sredA + r1*4);
        float wa = __expf(dla - dmaxa);
        float wb = __expf(dlb - dmaxb);
        y0 *= wa;
        y1 *= wb;

        // ymax reduction
        float wya = warpmax_(y0);
        float wyb = warpmax_(y1);
        if (lane == 0){ sredB[r0*4 + wl] = wya; sredB[r1*4 + wl] = wyb; }
        __syncthreads();                       // S2
        float ymaxa = max4s(sredB + r0*4);
        float ymaxb = max4s(sredB + r1*4);
        float lsolda = sls[r0];
        float lsoldb = sls[r1];

        // fractional-mask blend, computed unconditionally (uniform control flow)
        float bla = mka * (lsolda + dmaxa + __logf(fmaxf(y0, 1e-37f)))
                  + (1.0f - mka) * (lsolda + __logf(fmaxf(aolda, 1e-37f)));
        float blb = mkb * (lsoldb + dmaxb + __logf(fmaxf(y1, 1e-37f)))
                  + (1.0f - mkb) * (lsoldb + __logf(fmaxf(aoldb, 1e-37f)));
        float wba = warpmax_(bla);
        float wbb = warpmax_(blb);
        if (lane == 0){ sredA[r0*4 + wl] = wba; sredA[r1*4 + wl] = wbb; }
        __syncthreads();                       // S3
        float bmaxa = max4s(sredA + r0*4);
        float bmaxb = max4s(sredA + r1*4);

        float vna, vnb, lsna, lsnb;
        if (mka == 1.0f){
            vna = y0 * (1.0f / ymaxa);
            lsna = lsolda + dmaxa + __logf(ymaxa);
        } else if (mka == 0.0f){
            vna = aolda;
            lsna = lsolda;
        } else {
            vna = __expf(bla - bmaxa);
            lsna = bmaxa;
        }
        if (mkb == 1.0f){
            vnb = y1 * (1.0f / ymaxb);
            lsnb = lsoldb + dmaxb + __logf(ymaxb);
        } else if (mkb == 0.0f){
            vnb = aoldb;
            lsnb = lsoldb;
        } else {
            vnb = __expf(blb - bmaxb);
            lsnb = bmaxb;
        }

        sa[r0*S_ + n] = vna;
        sa[r1*S_ + n] = vnb;
        if (tid == 0 || tid == 128){
            sls[r0] = lsna;
            sls[r1] = lsnb;
        }
        __syncthreads();                       // S4
    }

    // objective per row: ls + log(sum_s a)
    {
        float sva = sa[r0*S_ + n];
        float svb = sa[r1*S_ + n];
        float wsa = warpsum_(sva);
        float wsb = warpsum_(svb);
        if (lane == 0){ sredA[r0*4 + wl] = wsa; sredA[r1*4 + wl] = wsb; }
        __syncthreads();
        if (tid == 0 || tid == 128){
            g_rowobj[b0 + r0] = sls[r0] + __logf(sum4s(sredA + r0*4));
            g_rowobj[b0 + r1] = sls[r1] + __logf(sum4s(sredA + r1*4));
        }
    }
}

// deterministic final reduction
__global__ void finalize_kernel(float* __restrict__ out, int out_size){
    __shared__ float sred[512];
    int t = threadIdx.x;
    sred[t] = g_rowobj[t];
    __syncthreads();
    for (int o = 256; o > 0; o >>= 1){
        if (t < o) sred[t] += sred[t+o];
        __syncthreads();
    }
    for (int i = t; i < out_size; i += 512){
        out[i] = (i == 0) ? sred[0] : 0.0f;
    }
}

// ============================ launch ============================

extern "C" void kernel_launch(void* const* d_in, const int* in_sizes, int n_in,
                              void* d_out, int out_size){
    const float* sents   = (const float*)d_in[0];  // (L,B,D)
    const float* masks   = (const float*)d_in[1];  // (L,B)
    const float* tparams = (const float*)d_in[2];  // (S,S)
    const float* means   = (const float*)d_in[3];  // (S,D)
    const float* var     = (const float*)d_in[4];  // (D,)

    cudaFuncSetAttribute(forward_kernel,
                         cudaFuncAttributeMaxDynamicSharedMemorySize, FWD_SMEM_BYTES);

    prep_var_kernel<<<1, 512>>>(var);
    prep_A_kernel<<<S_, 128>>>(tparams);
    prep_W_kernel<<<S_, 128>>>(means);
    gemm_kernel<<<NROWS/128, 256>>>(sents);
    forward_kernel<<<B_/4, 256, FWD_SMEM_BYTES>>>(masks);
    finalize_kernel<<<1, 512>>>((float*)d_out, out_size);
}

// round 5
// speedup vs baseline: 2.5333x; 1.2037x over previous
#include <cuda_runtime.h>
#include <cuda_bf16.h>
#include <math.h>

typedef unsigned int u32;

#define L_ 128
#define B_ 512
#define D_ 512
#define S_ 128
#define NROWS (L_*B_)

// ---- device scratch (static: no allocation allowed) ----
__device__ __nv_bfloat16 g_Wbf[S_*D_];       // Wt[s][d] = means[s][d]/var[d] (bf16)
__device__ float g_A[S_*S_];                 // row-stochastic transition matrix
__device__ float g_mm[S_];                   // sum_d means^2/var
__device__ float g_ivar[D_];
__device__ float g_scal[1];                  // ldc
__device__ float g_dens[(size_t)NROWS*S_];   // FULL log-density (33.5 MB)
__device__ float g_rowobj[B_];

// ============================ prep kernels ============================

__global__ void prep_var_kernel(const float* __restrict__ var){
    __shared__ float sred[512];
    int t = threadIdx.x;
    float v = var[t];
    g_ivar[t] = 1.0f / v;
    sred[t] = logf(v);
    __syncthreads();
    for (int o = 256; o > 0; o >>= 1){
        if (t < o) sred[t] += sred[t + o];
        __syncthreads();
    }
    if (t == 0){
        g_scal[0] = -(float)(D_/2) * logf(2.0f * 3.14159265358979323846f) - 0.5f * sred[0];
    }
}

__global__ void prep_A_kernel(const float* __restrict__ tp){
    __shared__ float sred[128];
    int s = blockIdx.x;
    int t = threadIdx.x;
    float v = tp[s*S_ + t];
    sred[t] = v;
    __syncthreads();
    for (int o = 64; o > 0; o >>= 1){
        if (t < o) sred[t] = fmaxf(sred[t], sred[t+o]);
        __syncthreads();
    }
    float mx = sred[0];
    __syncthreads();
    float e = expf(v - mx);
    sred[t] = e;
    __syncthreads();
    for (int o = 64; o > 0; o >>= 1){
        if (t < o) sred[t] += sred[t+o];
        __syncthreads();
    }
    g_A[s*S_ + t] = e / sred[0];
}

__global__ void prep_W_kernel(const float* __restrict__ means){
    __shared__ float sred[128];
    int s = blockIdx.x;
    int t = threadIdx.x;
    float acc = 0.0f;
    for (int d = t; d < D_; d += 128){
        float m = means[s*D_ + d];
        float w = m * g_ivar[d];
        g_Wbf[s*D_ + d] = __float2bfloat16(w);
        acc += m * w;
    }
    sred[t] = acc;
    __syncthreads();
    for (int o = 64; o > 0; o >>= 1){
        if (t < o) sred[t] += sred[t+o];
        __syncthreads();
    }
    if (t == 0) g_mm[s] = sred[0];
}

// ============================ phase 1: tensor-core GEMM ============================

__device__ __forceinline__ u32 swz(u32 off){
    return off ^ ((off >> 3) & 0x70u);
}

__device__ __forceinline__ void ldsm_x4(u32* r, u32 saddr){
    asm volatile("ldmatrix.sync.aligned.m8n8.x4.shared.b16 {%0,%1,%2,%3}, [%4];"
        : "=r"(r[0]), "=r"(r[1]), "=r"(r[2]), "=r"(r[3]) : "r"(saddr));
}

__device__ __forceinline__ void mma_bf16(float* c, const u32* a, u32 b0, u32 b1){
    asm volatile("mma.sync.aligned.m16n8k16.row.col.f32.bf16.bf16.f32 "
        "{%0,%1,%2,%3}, {%4,%5,%6,%7}, {%8,%9}, {%0,%1,%2,%3};"
        : "+f"(c[0]), "+f"(c[1]), "+f"(c[2]), "+f"(c[3])
        : "r"(a[0]), "r"(a[1]), "r"(a[2]), "r"(a[3]), "r"(b0), "r"(b1));
}

__device__ __forceinline__ u32 packbf(float x, float y){
    __nv_bfloat162 p = __floats2bfloat162_rn(x, y);
    return *(u32*)&p;
}

__global__ void __launch_bounds__(256) gemm_kernel(const float* __restrict__ X){
    __shared__ __align__(128) unsigned char smA[128*128];
    __shared__ __align__(128) unsigned char smB[128*128];
    __shared__ float sxx[128][16];
    __shared__ float sxxr[128];

    const int tid  = threadIdx.x;
    const int lane = tid & 31;
    const int warp = tid >> 5;
    const int warp_m = (warp >> 1) * 32;
    const int warp_n = (warp & 1) * 64;
    const size_t m0 = (size_t)blockIdx.x * 128;

    const u32 aBase = (u32)__cvta_generic_to_shared(smA);
    const u32 bBase = (u32)__cvta_generic_to_shared(smB);

    float acc[2][8][4];
    #pragma unroll
    for (int t = 0; t < 2; t++){
        #pragma unroll
        for (int j = 0; j < 8; j++){
            #pragma unroll
            for (int c = 0; c < 4; c++){ acc[t][j][c] = 0.0f; }
        }
    }
    float xacc[8];
    #pragma unroll
    for (int i = 0; i < 8; i++){ xacc[i] = 0.0f; }

    const int arow0 = tid >> 4;
    const int acol4 = tid & 15;
    const int brow0 = tid >> 3;
    const int bchk  = tid & 7;

    float4 xr[8];
    uint4  br[4];
    float4 ivr;

    {
        const int k0 = 0;
        ivr = *(const float4*)(g_ivar + k0 + acol4*4);
        #pragma unroll
        for (int i = 0; i < 8; i++){
            xr[i] = *(const float4*)(X + (m0 + arow0 + i*16)*D_ + k0 + acol4*4);
        }
        #pragma unroll
        for (int i = 0; i < 4; i++){
            br[i] = *(const uint4*)((const unsigned char*)g_Wbf + (size_t)(brow0 + i*32)*(D_*2) + k0*2 + bchk*16);
        }
    }

    for (int kt = 0; kt < 8; kt++){
        #pragma unroll
        for (int i = 0; i < 8; i++){
            int r = arow0 + i*16;
            float4 v = xr[i];
            xacc[i] += v.x*v.x*ivr.x + v.y*v.y*ivr.y + v.z*v.z*ivr.z + v.w*v.w*ivr.w;
            uint2 pk;
            pk.x = packbf(v.x, v.y);
            pk.y = packbf(v.z, v.w);
            u32 off = (u32)(r*128 + acol4*8);
            *(uint2*)(smA + swz(off)) = pk;
        }
        #pragma unroll
        for (int i = 0; i < 4; i++){
            int r = brow0 + i*32;
            u32 off = (u32)(r*128 + bchk*16);
            *(uint4*)(smB + swz(off)) = br[i];
        }
        __syncthreads();

        if (kt < 7){
            const int k0 = (kt + 1) * 64;
            ivr = *(const float4*)(g_ivar + k0 + acol4*4);
            #pragma unroll
            for (int i = 0; i < 8; i++){
                xr[i] = *(const float4*)(X + (m0 + arow0 + i*16)*D_ + k0 + acol4*4);
            }
            #pragma unroll
            for (int i = 0; i < 4; i++){
                br[i] = *(const uint4*)((const unsigned char*)g_Wbf + (size_t)(brow0 + i*32)*(D_*2) + k0*2 + bchk*16);
            }
        }

        #pragma unroll
        for (int kk = 0; kk < 4; kk++){
            u32 af[2][4];
            #pragma unroll
            for (int t = 0; t < 2; t++){
                u32 row = (u32)(warp_m + t*16 + (lane & 15));
                u32 off = row*128u + (u32)(kk*32) + (u32)((lane >> 4)*16);
                ldsm_x4(af[t], aBase + swz(off));
            }
            u32 bf[4][4];
            #pragma unroll
            for (int g = 0; g < 4; g++){
                u32 row = (u32)(warp_n + g*16 + (lane >> 4)*8 + (lane & 7));
                u32 off = row*128u + (u32)(kk*32) + (u32)(((lane >> 3) & 1)*16);
                ldsm_x4(bf[g], bBase + swz(off));
            }
            #pragma unroll
            for (int t = 0; t < 2; t++){
                #pragma unroll
                for (int g = 0; g < 4; g++){
                    mma_bf16(acc[t][g*2+0], af[t], bf[g][0], bf[g][1]);
                    mma_bf16(acc[t][g*2+1], af[t], bf[g][2], bf[g][3]);
                }
            }
        }
        __syncthreads();
    }

    #pragma unroll
    for (int i = 0; i < 8; i++){ sxx[arow0 + i*16][acol4] = xacc[i]; }
    __syncthreads();
    if (tid < 128){
        float s = 0.0f;
        #pragma unroll
        for (int c = 0; c < 16; c++){ s += sxx[tid][c]; }
        sxxr[tid] = s;
    }
    __syncthreads();

    const float ldc = g_scal[0];
    #pragma unroll
    for (int t = 0; t < 2; t++){
        int rl = warp_m + t*16 + (lane >> 2);
        float bias0 = ldc - 0.5f * sxxr[rl];
        float bias1 = ldc - 0.5f * sxxr[rl + 8];
        #pragma unroll
        for (int j = 0; j < 8; j++){
            int n = warp_n + j*8 + (lane & 3)*2;
            float mm0 = 0.5f * g_mm[n];
            float mm1 = 0.5f * g_mm[n+1];
            float2 o0;
            float2 o1;
            o0.x = acc[t][j][0] - mm0 + bias0;
            o0.y = acc[t][j][1] - mm1 + bias0;
            o1.x = acc[t][j][2] - mm0 + bias1;
            o1.y = acc[t][j][3] - mm1 + bias1;
            *(float2*)(g_dens + (m0 + rl)*S_ + n)     = o0;
            *(float2*)(g_dens + (m0 + rl + 8)*S_ + n) = o1;
        }
    }
}

// ============================ phase 2: tensor-core recursion ============================
// 32 CTAs x 256 threads. Each CTA: 16 batch rows. Each warp: 16 states (columns).
// Per step: y(16x128) = a(16x128, bf16 in smem) x A(128x128, bf16 frags in regs).

__device__ __forceinline__ float qmax_(float v){
    v = fmaxf(v, __shfl_xor_sync(0xffffffffu, v, 1));
    v = fmaxf(v, __shfl_xor_sync(0xffffffffu, v, 2));
    return v;
}
__device__ __forceinline__ float qsum_(float v){
    v += __shfl_xor_sync(0xffffffffu, v, 1);
    v += __shfl_xor_sync(0xffffffffu, v, 2);
    return v;
}
__device__ __forceinline__ float red8max(const float* p){
    return fmaxf(fmaxf(fmaxf(p[0], p[1]), fmaxf(p[2], p[3])),
                 fmaxf(fmaxf(p[4], p[5]), fmaxf(p[6], p[7])));
}
__device__ __forceinline__ float red8sum(const float* p){
    return ((p[0] + p[1]) + (p[2] + p[3])) + ((p[4] + p[5]) + (p[6] + p[7]));
}

#define APK_STRIDE 68

__global__ void __launch_bounds__(256) forward_kernel(const float* __restrict__ masks){
    __shared__ u32   aPk[16*APK_STRIDE];
    __shared__ float sredD[16*8];
    __shared__ float sredY[16*8];
    __shared__ float smk[2][16];
    __shared__ float sfracS[2];

    const int tid  = threadIdx.x;
    const int lane = tid & 31;
    const int warp = tid >> 5;
    const int q    = lane >> 2;       // 0..7
    const int c2   = lane & 3;        // 0..3
    const int b0   = blockIdx.x * 16;
    const int nc0  = warp*16 + c2*2;          // n8=0 column pair base
    const int nc1  = warp*16 + 8 + c2*2;      // n8=1 column pair base
    const float log_pi = -4.852030263919617f; // -log(128)

    // ---- constant B fragments: A[s][n] for this warp's 16 columns ----
    u32 bfr[8][2][2];
    #pragma unroll
    for (int kt = 0; kt < 8; kt++){
        #pragma unroll
        for (int n8 = 0; n8 < 2; n8++){
            int n  = warp*16 + n8*8 + q;
            int k0 = kt*16 + c2*2;
            bfr[kt][n8][0] = packbf(g_A[(k0+0)*S_ + n], g_A[(k0+1)*S_ + n]);
            bfr[kt][n8][1] = packbf(g_A[(k0+8)*S_ + n], g_A[(k0+9)*S_ + n]);
        }
    }

    float ls0, ls1;           // log-scales for rows b0+q, b0+q+8 (replicated per thread)
    float ac[2][4];           // fp32 alpha at this thread's output slots [n8][c]
    float dl[2][4];           // densities for current step

    // ---- t = 0 ----
    {
        float2 v;
        v = *(const float2*)(g_dens + (size_t)(b0 + q    )*S_ + nc0); dl[0][0]=v.x; dl[0][1]=v.y;
        v = *(const float2*)(g_dens + (size_t)(b0 + q + 8)*S_ + nc0); dl[0][2]=v.x; dl[0][3]=v.y;
        v = *(const float2*)(g_dens + (size_t)(b0 + q    )*S_ + nc1); dl[1][0]=v.x; dl[1][1]=v.y;
        v = *(const float2*)(g_dens + (size_t)(b0 + q + 8)*S_ + nc1); dl[1][2]=v.x; dl[1][3]=v.y;

        float vq  = fmaxf(fmaxf(dl[0][0], dl[0][1]), fmaxf(dl[1][0], dl[1][1]));
        float vq8 = fmaxf(fmaxf(dl[0][2], dl[0][3]), fmaxf(dl[1][2], dl[1][3]));
        vq = qmax_(vq); vq8 = qmax_(vq8);
        if (c2 == 0){ sredD[q*8 + warp] = vq; sredD[(q+8)*8 + warp] = vq8; }
        __syncthreads();
        float dmax0 = red8max(sredD + q*8);
        float dmax1 = red8max(sredD + (q+8)*8);
        #pragma unroll
        for (int n8 = 0; n8 < 2; n8++){
            ac[n8][0] = __expf(dl[n8][0] - dmax0);
            ac[n8][1] = __expf(dl[n8][1] - dmax0);
            ac[n8][2] = __expf(dl[n8][2] - dmax1);
            ac[n8][3] = __expf(dl[n8][3] - dmax1);
        }
        ls0 = log_pi + dmax0;
        ls1 = log_pi + dmax1;
        aPk[ q   *APK_STRIDE + warp*8 + 0 + c2] = packbf(ac[0][0], ac[0][1]);
        aPk[(q+8)*APK_STRIDE + warp*8 + 0 + c2] = packbf(ac[0][2], ac[0][3]);
        aPk[ q   *APK_STRIDE + warp*8 + 4 + c2] = packbf(ac[1][0], ac[1][1]);
        aPk[(q+8)*APK_STRIDE + warp*8 + 4 + c2] = packbf(ac[1][2], ac[1][3]);
    }

    // prefetch step-1 densities + masks
    {
        float2 v;
        size_t base = (size_t)(1*B_ + b0);
        v = *(const float2*)(g_dens + (base + q    )*S_ + nc0); dl[0][0]=v.x; dl[0][1]=v.y;
        v = *(const float2*)(g_dens + (base + q + 8)*S_ + nc0); dl[0][2]=v.x; dl[0][3]=v.y;
        v = *(const float2*)(g_dens + (base + q    )*S_ + nc1); dl[1][0]=v.x; dl[1][1]=v.y;
        v = *(const float2*)(g_dens + (base + q + 8)*S_ + nc1); dl[1][2]=v.x; dl[1][3]=v.y;
        if (warp == 0){
            float mv = (lane < 16) ? masks[1*B_ + b0 + lane] : 1.0f;
            if (lane < 16) smk[1][lane] = mv;
            u32 bal = __ballot_sync(0xffffffffu, (mv != 0.0f) && (mv != 1.0f) && (lane < 16));
            if (lane == 0) sfracS[1] = (bal != 0u) ? 1.0f : 0.0f;
        }
    }
    __syncthreads();   // aPk + smk visible

    for (int t = 1; t < L_; t++){
        const int buf = t & 1;

        // a-fragments from packed smem (conflict-free, stride 68)
        u32 af[8][4];
        #pragma unroll
        for (int kt = 0; kt < 8; kt++){
            af[kt][0] = aPk[ q   *APK_STRIDE + kt*8 + c2];
            af[kt][1] = aPk[(q+8)*APK_STRIDE + kt*8 + c2];
            af[kt][2] = aPk[ q   *APK_STRIDE + kt*8 + c2 + 4];
            af[kt][3] = aPk[(q+8)*APK_STRIDE + kt*8 + c2 + 4];
        }

        // prefetch next step (dens + masks) while MMAs run
        float dn[2][4];
        if (t + 1 < L_){
            float2 v;
            size_t base = (size_t)((t+1)*B_ + b0);
            v = *(const float2*)(g_dens + (base + q    )*S_ + nc0); dn[0][0]=v.x; dn[0][1]=v.y;
            v = *(const float2*)(g_dens + (base + q + 8)*S_ + nc0); dn[0][2]=v.x; dn[0][3]=v.y;
            v = *(const float2*)(g_dens + (base + q    )*S_ + nc1); dn[1][0]=v.x; dn[1][1]=v.y;
            v = *(const float2*)(g_dens + (base + q + 8)*S_ + nc1); dn[1][2]=v.x; dn[1][3]=v.y;
            if (warp == 0){
                float mv = (lane < 16) ? masks[(t+1)*B_ + b0 + lane] : 1.0f;
                if (lane < 16) smk[(t+1)&1][lane] = mv;
                u32 bal = __ballot_sync(0xffffffffu, (mv != 0.0f) && (mv != 1.0f) && (lane < 16));
                if (lane == 0) sfracS[(t+1)&1] = (bal != 0u) ? 1.0f : 0.0f;
            }
        }

        // y = a x A
        float acc[2][4];
        #pragma unroll
        for (int n8 = 0; n8 < 2; n8++){
            #pragma unroll
            for (int c = 0; c < 4; c++){ acc[n8][c] = 0.0f; }
        }
        #pragma unroll
        for (int kt = 0; kt < 8; kt++){
            mma_bf16(acc[0], af[kt], bfr[kt][0][0], bfr[kt][0][1]);
            mma_bf16(acc[1], af[kt], bfr[kt][1][0], bfr[kt][1][1]);
        }

        // dmax per row
        float vq  = fmaxf(fmaxf(dl[0][0], dl[0][1]), fmaxf(dl[1][0], dl[1][1]));
        float vq8 = fmaxf(fmaxf(dl[0][2], dl[0][3]), fmaxf(dl[1][2], dl[1][3]));
        vq = qmax_(vq); vq8 = qmax_(vq8);
        if (c2 == 0){ sredD[q*8 + warp] = vq; sredD[(q+8)*8 + warp] = vq8; }
        __syncthreads();                                           // S1
        float dmax0 = red8max(sredD + q*8);
        float dmax1 = red8max(sredD + (q+8)*8);

        // yw = y * exp(dl - dmax)
        #pragma unroll
        for (int n8 = 0; n8 < 2; n8++){
            acc[n8][0] *= __expf(dl[n8][0] - dmax0);
            acc[n8][1] *= __expf(dl[n8][1] - dmax0);
            acc[n8][2] *= __expf(dl[n8][2] - dmax1);
            acc[n8][3] *= __expf(dl[n8][3] - dmax1);
        }

        // ymax per row
        float mq  = fmaxf(fmaxf(acc[0][0], acc[0][1]), fmaxf(acc[1][0], acc[1][1]));
        float mq8 = fmaxf(fmaxf(acc[0][2], acc[0][3]), fmaxf(acc[1][2], acc[1][3]));
        mq = qmax_(mq); mq8 = qmax_(mq8);
        if (c2 == 0){ sredY[q*8 + warp] = mq; sredY[(q+8)*8 + warp] = mq8; }
        __syncthreads();                                           // S2
        float ymax0 = red8max(sredY + q*8);
        float ymax1 = red8max(sredY + (q+8)*8);

        float mk0 = smk[buf][q];
        float mk1 = smk[buf][q+8];
        float inv0 = __fdividef(1.0f, ymax0);
        float inv1 = __fdividef(1.0f, ymax1);

        bool one0 = (mk0 == 1.0f);
        bool one1 = (mk1 == 1.0f);
        float vnew[2][4];
        #pragma unroll
        for (int n8 = 0; n8 < 2; n8++){
            vnew[n8][0] = one0 ? acc[n8][0]*inv0 : ac[n8][0];
            vnew[n8][1] = one0 ? acc[n8][1]*inv0 : ac[n8][1];
            vnew[n8][2] = one1 ? acc[n8][2]*inv1 : ac[n8][2];
            vnew[n8][3] = one1 ? acc[n8][3]*inv1 : ac[n8][3];
        }
        float ls0n = one0 ? (ls0 + dmax0 + __logf(ymax0)) : ls0;
        float ls1n = one1 ? (ls1 + dmax1 + __logf(ymax1)) : ls1;

        // fractional-mask path (block-uniform branch; unused when masks are 0/1)
        if (sfracS[buf] != 0.0f){
            float bl[2][4];
            #pragma unroll
            for (int n8 = 0; n8 < 2; n8++){
                bl[n8][0] = mk0*(ls0 + dmax0 + __logf(fmaxf(acc[n8][0], 1e-37f)))
                          + (1.0f-mk0)*(ls0 + __logf(fmaxf(ac[n8][0], 1e-37f)));
                bl[n8][1] = mk0*(ls0 + dmax0 + __logf(fmaxf(acc[n8][1], 1e-37f)))
                          + (1.0f-mk0)*(ls0 + __logf(fmaxf(ac[n8][1], 1e-37f)));
                bl[n8][2] = mk1*(ls1 + dmax1 + __logf(fmaxf(acc[n8][2], 1e-37f)))
                          + (1.0f-mk1)*(ls1 + __logf(fmaxf(ac[n8][2], 1e-37f)));
                bl[n8][3] = mk1*(ls1 + dmax1 + __logf(fmaxf(acc[n8][3], 1e-37f)))
                          + (1.0f-mk1)*(ls1 + __logf(fmaxf(ac[n8][3], 1e-37f)));
            }
            float bq  = fmaxf(fmaxf(bl[0][0], bl[0][1]), fmaxf(bl[1][0], bl[1][1]));
            float bq8 = fmaxf(fmaxf(bl[0][2], bl[0][3]), fmaxf(bl[1][2], bl[1][3]));
            bq = qmax_(bq); bq8 = qmax_(bq8);
            if (c2 == 0){ sredD[q*8 + warp] = bq; sredD[(q+8)*8 + warp] = bq8; }
            __syncthreads();
            float bmax0 = red8max(sredD + q*8);
            float bmax1 = red8max(sredD + (q+8)*8);
            bool fr0 = (mk0 != 0.0f) && (mk0 != 1.0f);
            bool fr1 = (mk1 != 0.0f) && (mk1 != 1.0f);
            #pragma unroll
            for (int n8 = 0; n8 < 2; n8++){
                if (fr0){
                    vnew[n8][0] = __expf(bl[n8][0] - bmax0);
                    vnew[n8][1] = __expf(bl[n8][1] - bmax0);
                }
                if (fr1){
                    vnew[n8][2] = __expf(bl[n8][2] - bmax1);
                    vnew[n8][3] = __expf(bl[n8][3] - bmax1);
                }
            }
            if (fr0) ls0n = bmax0;
            if (fr1) ls1n = bmax1;
        }

        // commit: bf16 to smem (fragment-direct layout), fp32 to regs
        aPk[ q   *APK_STRIDE + warp*8 + 0 + c2] = packbf(vnew[0][0], vnew[0][1]);
        aPk[(q+8)*APK_STRIDE + warp*8 + 0 + c2] = packbf(vnew[0][2], vnew[0][3]);
        aPk[ q   *APK_STRIDE + warp*8 + 4 + c2] = packbf(vnew[1][0], vnew[1][1]);
        aPk[(q+8)*APK_STRIDE + warp*8 + 4 + c2] = packbf(vnew[1][2], vnew[1][3]);
        #pragma unroll
        for (int n8 = 0; n8 < 2; n8++){
            #pragma unroll
            for (int c = 0; c < 4; c++){
                ac[n8][c] = vnew[n8][c];
                dl[n8][c] = dn[n8][c];
            }
        }
        ls0 = ls0n;
        ls1 = ls1n;
        __syncthreads();                                           // S3
    }

    // objective: ls + log(sum_n alpha)
    {
        float sq  = (ac[0][0] + ac[0][1]) + (ac[1][0] + ac[1][1]);
        float sq8 = (ac[0][2] + ac[0][3]) + (ac[1][2] + ac[1][3]);
        sq = qsum_(sq); sq8 = qsum_(sq8);
        if (c2 == 0){ sredY[q*8 + warp] = sq; sredY[(q+8)*8 + warp] = sq8; }
        __syncthreads();
        if (warp == 0 && c2 == 0){
            float s0 = red8sum(sredY + q*8);
            float s1 = red8sum(sredY + (q+8)*8);
            g_rowobj[b0 + q]     = ls0 + logf(s0);
            g_rowobj[b0 + q + 8] = ls1 + logf(s1);
        }
    }
}

// deterministic final reduction
__global__ void finalize_kernel(float* __restrict__ out, int out_size){
    __shared__ float sred[512];
    int t = threadIdx.x;
    sred[t] = g_rowobj[t];
    __syncthreads();
    for (int o = 256; o > 0; o >>= 1){
        if (t < o) sred[t] += sred[t+o];
        __syncthreads();
    }
    for (int i = t; i < out_size; i += 512){
        out[i] = (i == 0) ? sred[0] : 0.0f;
    }
}

// ============================ launch ============================

extern "C" void kernel_launch(void* const* d_in, const int* in_sizes, int n_in,
                              void* d_out, int out_size){
    const float* sents   = (const float*)d_in[0];  // (L,B,D)
    const float* masks   = (const float*)d_in[1];  // (L,B)
    const float* tparams = (const float*)d_in[2];  // (S,S)
    const float* means   = (const float*)d_in[3];  // (S,D)
    const float* var     = (const float*)d_in[4];  // (D,)

    prep_var_kernel<<<1, 512>>>(var);
    prep_A_kernel<<<S_, 128>>>(tparams);
    prep_W_kernel<<<S_, 128>>>(means);
    gemm_kernel<<<NROWS/128, 256>>>(sents);
    forward_kernel<<<B_/16, 256>>>(masks);
    finalize_kernel<<<1, 512>>>((float*)d_out, out_size);
}

// round 8
// speedup vs baseline: 3.1701x; 1.2514x over previous
#include <cuda_runtime.h>
#include <cuda_bf16.h>
#include <math.h>

typedef unsigned int u32;

#define L_ 128
#define B_ 512
#define D_ 512
#define S_ 128
#define NROWS (L_*B_)

// ---- device scratch (static: no allocation allowed) ----
__device__ __nv_bfloat16 g_Wbf[S_*D_];       // Wt[s][d] = means[s][d]/var[d] (bf16)
__device__ float g_A[S_*S_];                 // row-stochastic transition matrix
__device__ float g_mm[S_];                   // sum_d means^2/var
__device__ float g_ivar[D_];
__device__ float g_scal[1];                  // ldc
__device__ u32   g_wpk[(size_t)NROWS*64];    // w = exp(dens-dmax), bf16 pairs (16.7MB)
__device__ float g_dmax[NROWS];              // per-(t,b) row max of dens
__device__ float g_rowobj[B_];

// ============================ prep kernels ============================

__global__ void prep_var_kernel(const float* __restrict__ var){
    __shared__ float sred[512];
    int t = threadIdx.x;
    float v = var[t];
    g_ivar[t] = 1.0f / v;
    sred[t] = logf(v);
    __syncthreads();
    for (int o = 256; o > 0; o >>= 1){
        if (t < o) sred[t] += sred[t + o];
        __syncthreads();
    }
    if (t == 0){
        g_scal[0] = -(float)(D_/2) * logf(2.0f * 3.14159265358979323846f) - 0.5f * sred[0];
    }
}

__global__ void prep_A_kernel(const float* __restrict__ tp){
    __shared__ float sred[128];
    int s = blockIdx.x;
    int t = threadIdx.x;
    float v = tp[s*S_ + t];
    sred[t] = v;
    __syncthreads();
    for (int o = 64; o > 0; o >>= 1){
        if (t < o) sred[t] = fmaxf(sred[t], sred[t+o]);
        __syncthreads();
    }
    float mx = sred[0];
    __syncthreads();
    float e = expf(v - mx);
    sred[t] = e;
    __syncthreads();
    for (int o = 64; o > 0; o >>= 1){
        if (t < o) sred[t] += sred[t+o];
        __syncthreads();
    }
    g_A[s*S_ + t] = e / sred[0];
}

__global__ void prep_W_kernel(const float* __restrict__ means){
    __shared__ float sred[128];
    int s = blockIdx.x;
    int t = threadIdx.x;
    float acc = 0.0f;
    for (int d = t; d < D_; d += 128){
        float m = means[s*D_ + d];
        float w = m * g_ivar[d];
        g_Wbf[s*D_ + d] = __float2bfloat16(w);
        acc += m * w;
    }
    sred[t] = acc;
    __syncthreads();
    for (int o = 64; o > 0; o >>= 1){
        if (t < o) sred[t] += sred[t+o];
        __syncthreads();
    }
    if (t == 0) g_mm[s] = sred[0];
}

// ============================ helpers ============================

__device__ __forceinline__ u32 swz(u32 off){
    return off ^ ((off >> 3) & 0x70u);
}
__device__ __forceinline__ void ldsm_x4(u32* r, u32 saddr){
    asm volatile("ldmatrix.sync.aligned.m8n8.x4.shared.b16 {%0,%1,%2,%3}, [%4];"
        : "=r"(r[0]), "=r"(r[1]), "=r"(r[2]), "=r"(r[3]) : "r"(saddr));
}
__device__ __forceinline__ void mma_bf16(float* c, const u32* a, u32 b0, u32 b1){
    asm volatile("mma.sync.aligned.m16n8k16.row.col.f32.bf16.bf16.f32 "
        "{%0,%1,%2,%3}, {%4,%5,%6,%7}, {%8,%9}, {%0,%1,%2,%3};"
        : "+f"(c[0]), "+f"(c[1]), "+f"(c[2]), "+f"(c[3])
        : "r"(a[0]), "r"(a[1]), "r"(a[2]), "r"(a[3]), "r"(b0), "r"(b1));
}
__device__ __forceinline__ u32 packbf(float x, float y){
    __nv_bfloat162 p = __floats2bfloat162_rn(x, y);
    return *(u32*)&p;
}
__device__ __forceinline__ float2 unpackbf(u32 v){
    __nv_bfloat162 p = *(__nv_bfloat162*)&v;
    float2 r;
    r.x = __low2float(p);
    r.y = __high2float(p);
    return r;
}

// ============================ phase 1: tensor-core GEMM ============================
// Produces w = exp(dens - dmax) (bf16 pairs) and dmax per row.

__global__ void __launch_bounds__(256) gemm_kernel(const float* __restrict__ X){
    __shared__ __align__(128) unsigned char smA[128*128];
    __shared__ __align__(128) unsigned char smB[128*128];
    __shared__ float sxx[128][16];
    __shared__ float sxxr[128];
    __shared__ float sdm[128][2];

    const int tid  = threadIdx.x;
    const int lane = tid & 31;
    const int warp = tid >> 5;
    const int warp_m = (warp >> 1) * 32;
    const int warp_n = (warp & 1) * 64;
    const size_t m0 = (size_t)blockIdx.x * 128;

    const u32 aBase = (u32)__cvta_generic_to_shared(smA);
    const u32 bBase = (u32)__cvta_generic_to_shared(smB);

    float acc[2][8][4];
    #pragma unroll
    for (int t = 0; t < 2; t++){
        #pragma unroll
        for (int j = 0; j < 8; j++){
            #pragma unroll
            for (int c = 0; c < 4; c++){ acc[t][j][c] = 0.0f; }
        }
    }
    float xacc[8];
    #pragma unroll
    for (int i = 0; i < 8; i++){ xacc[i] = 0.0f; }

    const int arow0 = tid >> 4;
    const int acol4 = tid & 15;
    const int brow0 = tid >> 3;
    const int bchk  = tid & 7;

    float4 xr[8];
    uint4  br[4];
    float4 ivr;

    {
        const int k0 = 0;
        ivr = *(const float4*)(g_ivar + k0 + acol4*4);
        #pragma unroll
        for (int i = 0; i < 8; i++){
            xr[i] = *(const float4*)(X + (m0 + arow0 + i*16)*D_ + k0 + acol4*4);
        }
        #pragma unroll
        for (int i = 0; i < 4; i++){
            br[i] = *(const uint4*)((const unsigned char*)g_Wbf + (size_t)(brow0 + i*32)*(D_*2) + k0*2 + bchk*16);
        }
    }

    for (int kt = 0; kt < 8; kt++){
        #pragma unroll
        for (int i = 0; i < 8; i++){
            int r = arow0 + i*16;
            float4 v = xr[i];
            xacc[i] += v.x*v.x*ivr.x + v.y*v.y*ivr.y + v.z*v.z*ivr.z + v.w*v.w*ivr.w;
            uint2 pk;
            pk.x = packbf(v.x, v.y);
            pk.y = packbf(v.z, v.w);
            u32 off = (u32)(r*128 + acol4*8);
            *(uint2*)(smA + swz(off)) = pk;
        }
        #pragma unroll
        for (int i = 0; i < 4; i++){
            int r = brow0 + i*32;
            u32 off = (u32)(r*128 + bchk*16);
            *(uint4*)(smB + swz(off)) = br[i];
        }
        __syncthreads();

        if (kt < 7){
            const int k0 = (kt + 1) * 64;
            ivr = *(const float4*)(g_ivar + k0 + acol4*4);
            #pragma unroll
            for (int i = 0; i < 8; i++){
                xr[i] = *(const float4*)(X + (m0 + arow0 + i*16)*D_ + k0 + acol4*4);
            }
            #pragma unroll
            for (int i = 0; i < 4; i++){
                br[i] = *(const uint4*)((const unsigned char*)g_Wbf + (size_t)(brow0 + i*32)*(D_*2) + k0*2 + bchk*16);
            }
        }

        #pragma unroll
        for (int kk = 0; kk < 4; kk++){
            u32 af[2][4];
            #pragma unroll
            for (int t = 0; t < 2; t++){
                u32 row = (u32)(warp_m + t*16 + (lane & 15));
                u32 off = row*128u + (u32)(kk*32) + (u32)((lane >> 4)*16);
                ldsm_x4(af[t], aBase + swz(off));
            }
            u32 bf[4][4];
            #pragma unroll
            for (int g = 0; g < 4; g++){
                u32 row = (u32)(warp_n + g*16 + (lane >> 4)*8 + (lane & 7));
                u32 off = row*128u + (u32)(kk*32) + (u32)(((lane >> 3) & 1)*16);
                ldsm_x4(bf[g], bBase + swz(off));
            }
            #pragma unroll
            for (int t = 0; t < 2; t++){
                #pragma unroll
                for (int g = 0; g < 4; g++){
                    mma_bf16(acc[t][g*2+0], af[t], bf[g][0], bf[g][1]);
                    mma_bf16(acc[t][g*2+1], af[t], bf[g][2], bf[g][3]);
                }
            }
        }
        __syncthreads();
    }

    // per-row xx
    #pragma unroll
    for (int i = 0; i < 8; i++){ sxx[arow0 + i*16][acol4] = xacc[i]; }
    __syncthreads();
    if (tid < 128){
        float s = 0.0f;
        #pragma unroll
        for (int c = 0; c < 16; c++){ s += sxx[tid][c]; }
        sxxr[tid] = s;
    }
    __syncthreads();

    // epilogue: dens in-place, row max, then w = exp(dens - dmax) as bf16 pairs
    const float ldc = g_scal[0];
    #pragma unroll
    for (int t = 0; t < 2; t++){
        int rl = warp_m + t*16 + (lane >> 2);
        float bias0 = ldc - 0.5f * sxxr[rl];
        float bias1 = ldc - 0.5f * sxxr[rl + 8];
        float rm0 = -3.0e38f;
        float rm1 = -3.0e38f;
        #pragma unroll
        for (int j = 0; j < 8; j++){
            int n = warp_n + j*8 + (lane & 3)*2;
            float mm0 = 0.5f * g_mm[n];
            float mm1 = 0.5f * g_mm[n+1];
            acc[t][j][0] = acc[t][j][0] - mm0 + bias0;
            acc[t][j][1] = acc[t][j][1] - mm1 + bias0;
            acc[t][j][2] = acc[t][j][2] - mm0 + bias1;
            acc[t][j][3] = acc[t][j][3] - mm1 + bias1;
            rm0 = fmaxf(rm0, fmaxf(acc[t][j][0], acc[t][j][1]));
            rm1 = fmaxf(rm1, fmaxf(acc[t][j][2], acc[t][j][3]));
        }
        rm0 = fmaxf(rm0, __shfl_xor_sync(0xffffffffu, rm0, 1));
        rm0 = fmaxf(rm0, __shfl_xor_sync(0xffffffffu, rm0, 2));
        rm1 = fmaxf(rm1, __shfl_xor_sync(0xffffffffu, rm1, 1));
        rm1 = fmaxf(rm1, __shfl_xor_sync(0xffffffffu, rm1, 2));
        if ((lane & 3) == 0){
            sdm[rl][warp & 1] = rm0;
            sdm[rl + 8][warp & 1] = rm1;
        }
    }
    __syncthreads();
    #pragma unroll
    for (int t = 0; t < 2; t++){
        int rl = warp_m + t*16 + (lane >> 2);
        float dmax0 = fmaxf(sdm[rl][0],   sdm[rl][1]);
        float dmax1 = fmaxf(sdm[rl+8][0], sdm[rl+8][1]);
        #pragma unroll
        for (int j = 0; j < 8; j++){
            int p = warp_n/2 + j*4 + (lane & 3);
            g_wpk[(m0 + rl)*64 + p] =
                packbf(__expf(acc[t][j][0] - dmax0), __expf(acc[t][j][1] - dmax0));
            g_wpk[(m0 + rl + 8)*64 + p] =
                packbf(__expf(acc[t][j][2] - dmax1), __expf(acc[t][j][3] - dmax1));
        }
        if ((warp & 1) == 0 && (lane & 3) == 0){
            g_dmax[m0 + rl]     = dmax0;
            g_dmax[m0 + rl + 8] = dmax1;
        }
    }
}

// ============================ phase 2: tensor-core recursion (v3) ============================
// 32 CTAs x 256 threads. 16 rows/CTA, each warp owns 16 state columns.
// 1 barrier per step: lagged renormalization, precomputed w/dmax.

__device__ __forceinline__ float qmax_(float v){
    v = fmaxf(v, __shfl_xor_sync(0xffffffffu, v, 1));
    v = fmaxf(v, __shfl_xor_sync(0xffffffffu, v, 2));
    return v;
}
__device__ __forceinline__ float qsum_(float v){
    v += __shfl_xor_sync(0xffffffffu, v, 1);
    v += __shfl_xor_sync(0xffffffffu, v, 2);
    return v;
}
__device__ __forceinline__ float red8max(const float* p){
    return fmaxf(fmaxf(fmaxf(p[0], p[1]), fmaxf(p[2], p[3])),
                 fmaxf(fmaxf(p[4], p[5]), fmaxf(p[6], p[7])));
}
__device__ __forceinline__ float red8sum(const float* p){
    return ((p[0] + p[1]) + (p[2] + p[3])) + ((p[4] + p[5]) + (p[6] + p[7]));
}

#define APK_STRIDE 68

__global__ void __launch_bounds__(256) forward_kernel(const float* __restrict__ masks){
    __shared__ u32   aPk[2][16*APK_STRIDE];
    __shared__ float sredY[2][16*8];
    __shared__ float sredF[16*8];
    __shared__ float smk[2][16];
    __shared__ float sfracS[2];

    const int tid  = threadIdx.x;
    const int lane = tid & 31;
    const int warp = tid >> 5;
    const int q    = lane >> 2;
    const int c2   = lane & 3;
    const int b0   = blockIdx.x * 16;
    const int p0   = warp*8 + c2;
    const int p1   = warp*8 + 4 + c2;
    const float log_pi = -4.852030263919617f; // -log(128)

    // constant transition-matrix fragments
    u32 bfr[8][2][2];
    #pragma unroll
    for (int kt = 0; kt < 8; kt++){
        #pragma unroll
        for (int n8 = 0; n8 < 2; n8++){
            int n  = warp*16 + n8*8 + q;
            int k0 = kt*16 + c2*2;
            bfr[kt][n8][0] = packbf(g_A[(k0+0)*S_ + n], g_A[(k0+1)*S_ + n]);
            bfr[kt][n8][1] = packbf(g_A[(k0+8)*S_ + n], g_A[(k0+9)*S_ + n]);
        }
    }

    float ls0, ls1;
    float ac[2][4];
    u32 wq[4];
    u32 wqn[4] = {0u, 0u, 0u, 0u};
    float dmc0, dmc1;
    float dmn0 = 0.0f, dmn1 = 0.0f;

    // ---- t = 0 ----
    {
        size_t r0 = (size_t)(b0 + q)*64;
        size_t r1 = (size_t)(b0 + q + 8)*64;
        wq[0] = g_wpk[r0 + p0];
        wq[1] = g_wpk[r1 + p0];
        wq[2] = g_wpk[r0 + p1];
        wq[3] = g_wpk[r1 + p1];
        float dm0 = g_dmax[b0 + q];
        float dm1 = g_dmax[b0 + q + 8];
        float2 v;
        v = unpackbf(wq[0]); ac[0][0] = v.x; ac[0][1] = v.y;
        v = unpackbf(wq[1]); ac[0][2] = v.x; ac[0][3] = v.y;
        v = unpackbf(wq[2]); ac[1][0] = v.x; ac[1][1] = v.y;
        v = unpackbf(wq[3]); ac[1][2] = v.x; ac[1][3] = v.y;
        ls0 = log_pi + dm0;
        ls1 = log_pi + dm1;
        // alpha0 = w (bf16 exact copy)
        aPk[0][ q   *APK_STRIDE + p0] = wq[0];
        aPk[0][(q+8)*APK_STRIDE + p0] = wq[1];
        aPk[0][ q   *APK_STRIDE + p1] = wq[2];
        aPk[0][(q+8)*APK_STRIDE + p1] = wq[3];
        float mq  = qmax_(fmaxf(fmaxf(ac[0][0], ac[0][1]), fmaxf(ac[1][0], ac[1][1])));
        float mq8 = qmax_(fmaxf(fmaxf(ac[0][2], ac[0][3]), fmaxf(ac[1][2], ac[1][3])));
        if (c2 == 0){ sredY[0][q*8 + warp] = mq; sredY[0][(q+8)*8 + warp] = mq8; }

        // prefetch t=1
        size_t n0 = (size_t)(B_ + b0 + q)*64;
        size_t n1 = (size_t)(B_ + b0 + q + 8)*64;
        wq[0] = g_wpk[n0 + p0];
        wq[1] = g_wpk[n1 + p0];
        wq[2] = g_wpk[n0 + p1];
        wq[3] = g_wpk[n1 + p1];
        dmc0 = g_dmax[B_ + b0 + q];
        dmc1 = g_dmax[B_ + b0 + q + 8];
        if (warp == 0){
            float mv = (lane < 16) ? masks[B_ + b0 + lane] : 1.0f;
            if (lane < 16) smk[1][lane] = mv;
            u32 bal = __ballot_sync(0xffffffffu, (mv != 0.0f) && (mv != 1.0f) && (lane < 16));
            if (lane == 0) sfracS[1] = (bal != 0u) ? 1.0f : 0.0f;
        }
        __syncthreads();
    }

    for (int t = 1; t < L_; t++){
        const int cur = t & 1;
        const int prv = cur ^ 1;

        // lagged renorm factors from previous step's stored max
        float ym0 = red8max(&sredY[prv][q*8]);
        float ym1 = red8max(&sredY[prv][(q+8)*8]);
        float lg0 = __logf(ym0);
        float lg1 = __logf(ym1);
        float inv0 = __fdividef(1.0f, ym0);
        float inv1 = __fdividef(1.0f, ym1);

        // alpha fragments
        u32 af[8][4];
        #pragma unroll
        for (int kt = 0; kt < 8; kt++){
            af[kt][0] = aPk[prv][ q   *APK_STRIDE + kt*8 + c2];
            af[kt][1] = aPk[prv][(q+8)*APK_STRIDE + kt*8 + c2];
            af[kt][2] = aPk[prv][ q   *APK_STRIDE + kt*8 + 4 + c2];
            af[kt][3] = aPk[prv][(q+8)*APK_STRIDE + kt*8 + 4 + c2];
        }

        // prefetch t+1
        if (t + 1 < L_){
            size_t n0 = (size_t)((t+1)*B_ + b0 + q)*64;
            size_t n1 = (size_t)((t+1)*B_ + b0 + q + 8)*64;
            wqn[0] = g_wpk[n0 + p0];
            wqn[1] = g_wpk[n1 + p0];
            wqn[2] = g_wpk[n0 + p1];
            wqn[3] = g_wpk[n1 + p1];
            dmn0 = g_dmax[(t+1)*B_ + b0 + q];
            dmn1 = g_dmax[(t+1)*B_ + b0 + q + 8];
            if (warp == 0){
                float mv = (lane < 16) ? masks[(t+1)*B_ + b0 + lane] : 1.0f;
                if (lane < 16) smk[(t+1)&1][lane] = mv;
                u32 bal = __ballot_sync(0xffffffffu, (mv != 0.0f) && (mv != 1.0f) && (lane < 16));
                if (lane == 0) sfracS[(t+1)&1] = (bal != 0u) ? 1.0f : 0.0f;
            }
        }

        // y = a x A
        float acc[2][4];
        #pragma unroll
        for (int n8 = 0; n8 < 2; n8++){
            #pragma unroll
            for (int c = 0; c < 4; c++){ acc[n8][c] = 0.0f; }
        }
        #pragma unroll
        for (int kt = 0; kt < 8; kt++){
            mma_bf16(acc[0], af[kt], bfr[kt][0][0], bfr[kt][0][1]);
            mma_bf16(acc[1], af[kt], bfr[kt][1][0], bfr[kt][1][1]);
        }

        // multiply by w (pre-inv values kept for frac path)
        float2 v;
        v = unpackbf(wq[0]); acc[0][0] *= v.x; acc[0][1] *= v.y;
        v = unpackbf(wq[1]); acc[0][2] *= v.x; acc[0][3] *= v.y;
        v = unpackbf(wq[2]); acc[1][0] *= v.x; acc[1][1] *= v.y;
        v = unpackbf(wq[3]); acc[1][2] *= v.x; acc[1][3] *= v.y;

        float mk0 = smk[cur][q];
        float mk1 = smk[cur][q+8];
        bool one0 = (mk0 == 1.0f);
        bool one1 = (mk1 == 1.0f);

        float vnew[2][4];
        #pragma unroll
        for (int n8 = 0; n8 < 2; n8++){
            vnew[n8][0] = (one0 ? acc[n8][0] : ac[n8][0]) * inv0;
            vnew[n8][1] = (one0 ? acc[n8][1] : ac[n8][1]) * inv0;
            vnew[n8][2] = (one1 ? acc[n8][2] : ac[n8][2]) * inv1;
            vnew[n8][3] = (one1 ? acc[n8][3] : ac[n8][3]) * inv1;
        }
        float ls0n = one0 ? (ls0 + dmc0 + lg0) : (ls0 + lg0);
        float ls1n = one1 ? (ls1 + dmc1 + lg1) : (ls1 + lg1);

        // fractional-mask path (block-uniform, rare)
        if (sfracS[cur] != 0.0f){
            float bl[2][4];
            #pragma unroll
            for (int n8 = 0; n8 < 2; n8++){
                bl[n8][0] = mk0*(ls0 + dmc0 + __logf(fmaxf(acc[n8][0], 1e-37f)))
                          + (1.0f-mk0)*(ls0 + __logf(fmaxf(ac[n8][0], 1e-37f)));
                bl[n8][1] = mk0*(ls0 + dmc0 + __logf(fmaxf(acc[n8][1], 1e-37f)))
                          + (1.0f-mk0)*(ls0 + __logf(fmaxf(ac[n8][1], 1e-37f)));
                bl[n8][2] = mk1*(ls1 + dmc1 + __logf(fmaxf(acc[n8][2], 1e-37f)))
                          + (1.0f-mk1)*(ls1 + __logf(fmaxf(ac[n8][2], 1e-37f)));
                bl[n8][3] = mk1*(ls1 + dmc1 + __logf(fmaxf(acc[n8][3], 1e-37f)))
                          + (1.0f-mk1)*(ls1 + __logf(fmaxf(ac[n8][3], 1e-37f)));
            }
            float bq  = qmax_(fmaxf(fmaxf(bl[0][0], bl[0][1]), fmaxf(bl[1][0], bl[1][1])));
            float bq8 = qmax_(fmaxf(fmaxf(bl[0][2], bl[0][3]), fmaxf(bl[1][2], bl[1][3])));
            if (c2 == 0){ sredF[q*8 + warp] = bq; sredF[(q+8)*8 + warp] = bq8; }
            __syncthreads();
            float bmax0 = red8max(&sredF[q*8]);
            float bmax1 = red8max(&sredF[(q+8)*8]);
            bool fr0 = (mk0 != 0.0f) && (mk0 != 1.0f);
            bool fr1 = (mk1 != 0.0f) && (mk1 != 1.0f);
            #pragma unroll
            for (int n8 = 0; n8 < 2; n8++){
                if (fr0){
                    vnew[n8][0] = __expf(bl[n8][0] - bmax0);
                    vnew[n8][1] = __expf(bl[n8][1] - bmax0);
                }
                if (fr1){
                    vnew[n8][2] = __expf(bl[n8][2] - bmax1);
                    vnew[n8][3] = __expf(bl[n8][3] - bmax1);
                }
            }
            if (fr0) ls0n = bmax0;
            if (fr1) ls1n = bmax1;
        }

        // commit
        aPk[cur][ q   *APK_STRIDE + p0] = packbf(vnew[0][0], vnew[0][1]);
        aPk[cur][(q+8)*APK_STRIDE + p0] = packbf(vnew[0][2], vnew[0][3]);
        aPk[cur][ q   *APK_STRIDE + p1] = packbf(vnew[1][0], vnew[1][1]);
        aPk[cur][(q+8)*APK_STRIDE + p1] = packbf(vnew[1][2], vnew[1][3]);
        float mq  = qmax_(fmaxf(fmaxf(vnew[0][0], vnew[0][1]), fmaxf(vnew[1][0], vnew[1][1])));
        float mq8 = qmax_(fmaxf(fmaxf(vnew[0][2], vnew[0][3]), fmaxf(vnew[1][2], vnew[1][3])));
        if (c2 == 0){ sredY[cur][q*8 + warp] = mq; sredY[cur][(q+8)*8 + warp] = mq8; }

        #pragma unroll
        for (int n8 = 0; n8 < 2; n8++){
            #pragma unroll
            for (int c = 0; c < 4; c++){ ac[n8][c] = vnew[n8][c]; }
        }
        ls0 = ls0n;
        ls1 = ls1n;
        wq[0] = wqn[0]; wq[1] = wqn[1]; wq[2] = wqn[2]; wq[3] = wqn[3];
        dmc0 = dmn0;
        dmc1 = dmn1;
        __syncthreads();
    }

    // objective: ls + log(sum_n alpha)
    {
        float sq  = qsum_((ac[0][0] + ac[0][1]) + (ac[1][0] + ac[1][1]));
        float sq8 = qsum_((ac[0][2] + ac[0][3]) + (ac[1][2] + ac[1][3]));
        if (c2 == 0){ sredF[q*8 + warp] = sq; sredF[(q+8)*8 + warp] = sq8; }
        __syncthreads();
        if (warp == 0 && c2 == 0){
            float s0 = red8sum(&sredF[q*8]);
            float s1 = red8sum(&sredF[(q+8)*8]);
            g_rowobj[b0 + q]     = ls0 + logf(s0);
            g_rowobj[b0 + q + 8] = ls1 + logf(s1);
        }
    }
}

// deterministic final reduction
__global__ void finalize_kernel(float* __restrict__ out, int out_size){
    __shared__ float sred[512];
    int t = threadIdx.x;
    sred[t] = g_rowobj[t];
    __syncthreads();
    for (int o = 256; o > 0; o >>= 1){
        if (t < o) sred[t] += sred[t+o];
        __syncthreads();
    }
    for (int i = t; i < out_size; i += 512){
        out[i] = (i == 0) ? sred[0] : 0.0f;
    }
}

// ============================ launch ============================

extern "C" void kernel_launch(void* const* d_in, const int* in_sizes, int n_in,
                              void* d_out, int out_size){
    const float* sents   = (const float*)d_in[0];  // (L,B,D)
    const float* masks   = (const float*)d_in[1];  // (L,B)
    const float* tparams = (const float*)d_in[2];  // (S,S)
    const float* means   = (const float*)d_in[3];  // (S,D)
    const float* var     = (const float*)d_in[4];  // (D,)

    prep_var_kernel<<<1, 512>>>(var);
    prep_A_kernel<<<S_, 128>>>(tparams);
    prep_W_kernel<<<S_, 128>>>(means);
    gemm_kernel<<<NROWS/128, 256>>>(sents);
    forward_kernel<<<B_/16, 256>>>(masks);
    finalize_kernel<<<1, 512>>>((float*)d_out, out_size);
}

// round 11
// speedup vs baseline: 3.6615x; 1.1550x over previous
#include <cuda_runtime.h>
#include <cuda_bf16.h>
#include <math.h>

typedef unsigned int u32;

#define L_ 128
#define B_ 512
#define D_ 512
#define S_ 128
#define NROWS (L_*B_)

// ---- device scratch (static: no allocation allowed) ----
__device__ __nv_bfloat16 g_Wbf[S_*D_];       // Wt[s][d] = means[s][d]/var[d] (bf16)
__device__ float g_A[S_*S_];                 // row-stochastic transition matrix
__device__ float g_mm[S_];                   // sum_d means^2/var
__device__ float g_ivar[D_];
__device__ float g_scal[1];                  // ldc
__device__ u32   g_wpk[(size_t)NROWS*64];    // w = exp(dens-dmax), bf16 pairs (16.7MB)
__device__ float g_dmax[NROWS];              // per-(t,b) row max of dens
__device__ float g_rowobj[B_];

// ============================ prep kernels ============================

__global__ void prep_var_kernel(const float* __restrict__ var){
    __shared__ float sred[512];
    int t = threadIdx.x;
    float v = var[t];
    g_ivar[t] = 1.0f / v;
    sred[t] = logf(v);
    __syncthreads();
    for (int o = 256; o > 0; o >>= 1){
        if (t < o) sred[t] += sred[t + o];
        __syncthreads();
    }
    if (t == 0){
        g_scal[0] = -(float)(D_/2) * logf(2.0f * 3.14159265358979323846f) - 0.5f * sred[0];
    }
}

__global__ void prep_A_kernel(const float* __restrict__ tp){
    __shared__ float sred[128];
    int s = blockIdx.x;
    int t = threadIdx.x;
    float v = tp[s*S_ + t];
    sred[t] = v;
    __syncthreads();
    for (int o = 64; o > 0; o >>= 1){
        if (t < o) sred[t] = fmaxf(sred[t], sred[t+o]);
        __syncthreads();
    }
    float mx = sred[0];
    __syncthreads();
    float e = expf(v - mx);
    sred[t] = e;
    __syncthreads();
    for (int o = 64; o > 0; o >>= 1){
        if (t < o) sred[t] += sred[t+o];
        __syncthreads();
    }
    g_A[s*S_ + t] = e / sred[0];
}

__global__ void prep_W_kernel(const float* __restrict__ means){
    __shared__ float sred[128];
    int s = blockIdx.x;
    int t = threadIdx.x;
    float acc = 0.0f;
    for (int d = t; d < D_; d += 128){
        float m = means[s*D_ + d];
        float w = m * g_ivar[d];
        g_Wbf[s*D_ + d] = __float2bfloat16(w);
        acc += m * w;
    }
    sred[t] = acc;
    __syncthreads();
    for (int o = 64; o > 0; o >>= 1){
        if (t < o) sred[t] += sred[t+o];
        __syncthreads();
    }
    if (t == 0) g_mm[s] = sred[0];
}

// ============================ helpers ============================

__device__ __forceinline__ u32 swz(u32 off){
    return off ^ ((off >> 3) & 0x70u);
}
__device__ __forceinline__ void ldsm_x4(u32* r, u32 saddr){
    asm volatile("ldmatrix.sync.aligned.m8n8.x4.shared.b16 {%0,%1,%2,%3}, [%4];"
        : "=r"(r[0]), "=r"(r[1]), "=r"(r[2]), "=r"(r[3]) : "r"(saddr));
}
__device__ __forceinline__ void mma_bf16(float* c, const u32* a, u32 b0, u32 b1){
    asm volatile("mma.sync.aligned.m16n8k16.row.col.f32.bf16.bf16.f32 "
        "{%0,%1,%2,%3}, {%4,%5,%6,%7}, {%8,%9}, {%0,%1,%2,%3};"
        : "+f"(c[0]), "+f"(c[1]), "+f"(c[2]), "+f"(c[3])
        : "r"(a[0]), "r"(a[1]), "r"(a[2]), "r"(a[3]), "r"(b0), "r"(b1));
}
__device__ __forceinline__ u32 packbf(float x, float y){
    __nv_bfloat162 p = __floats2bfloat162_rn(x, y);
    return *(u32*)&p;
}
__device__ __forceinline__ float2 unpackbf(u32 v){
    __nv_bfloat162 p = *(__nv_bfloat162*)&v;
    float2 r;
    r.x = __low2float(p);
    r.y = __high2float(p);
    return r;
}

// ============================ phase 1: tensor-core GEMM ============================
// Produces w = exp(dens - dmax) (bf16 pairs) and dmax per row.

__global__ void __launch_bounds__(256) gemm_kernel(const float* __restrict__ X){
    __shared__ __align__(128) unsigned char smA[128*128];
    __shared__ __align__(128) unsigned char smB[128*128];
    __shared__ float sxx[128][16];
    __shared__ float sxxr[128];
    __shared__ float sdm[128][2];

    const int tid  = threadIdx.x;
    const int lane = tid & 31;
    const int warp = tid >> 5;
    const int warp_m = (warp >> 1) * 32;
    const int warp_n = (warp & 1) * 64;
    const size_t m0 = (size_t)blockIdx.x * 128;

    const u32 aBase = (u32)__cvta_generic_to_shared(smA);
    const u32 bBase = (u32)__cvta_generic_to_shared(smB);

    float acc[2][8][4];
    #pragma unroll
    for (int t = 0; t < 2; t++){
        #pragma unroll
        for (int j = 0; j < 8; j++){
            #pragma unroll
            for (int c = 0; c < 4; c++){ acc[t][j][c] = 0.0f; }
        }
    }
    float xacc[8];
    #pragma unroll
    for (int i = 0; i < 8; i++){ xacc[i] = 0.0f; }

    const int arow0 = tid >> 4;
    const int acol4 = tid & 15;
    const int brow0 = tid >> 3;
    const int bchk  = tid & 7;

    float4 xr[8];
    uint4  br[4];
    float4 ivr;

    {
        const int k0 = 0;
        ivr = *(const float4*)(g_ivar + k0 + acol4*4);
        #pragma unroll
        for (int i = 0; i < 8; i++){
            xr[i] = *(const float4*)(X + (m0 + arow0 + i*16)*D_ + k0 + acol4*4);
        }
        #pragma unroll
        for (int i = 0; i < 4; i++){
            br[i] = *(const uint4*)((const unsigned char*)g_Wbf + (size_t)(brow0 + i*32)*(D_*2) + k0*2 + bchk*16);
        }
    }

    for (int kt = 0; kt < 8; kt++){
        #pragma unroll
        for (int i = 0; i < 8; i++){
            int r = arow0 + i*16;
            float4 v = xr[i];
            xacc[i] += v.x*v.x*ivr.x + v.y*v.y*ivr.y + v.z*v.z*ivr.z + v.w*v.w*ivr.w;
            uint2 pk;
            pk.x = packbf(v.x, v.y);
            pk.y = packbf(v.z, v.w);
            u32 off = (u32)(r*128 + acol4*8);
            *(uint2*)(smA + swz(off)) = pk;
        }
        #pragma unroll
        for (int i = 0; i < 4; i++){
            int r = brow0 + i*32;
            u32 off = (u32)(r*128 + bchk*16);
            *(uint4*)(smB + swz(off)) = br[i];
        }
        __syncthreads();

        if (kt < 7){
            const int k0 = (kt + 1) * 64;
            ivr = *(const float4*)(g_ivar + k0 + acol4*4);
            #pragma unroll
            for (int i = 0; i < 8; i++){
                xr[i] = *(const float4*)(X + (m0 + arow0 + i*16)*D_ + k0 + acol4*4);
            }
            #pragma unroll
            for (int i = 0; i < 4; i++){
                br[i] = *(const uint4*)((const unsigned char*)g_Wbf + (size_t)(brow0 + i*32)*(D_*2) + k0*2 + bchk*16);
            }
        }

        #pragma unroll
        for (int kk = 0; kk < 4; kk++){
            u32 af[2][4];
            #pragma unroll
            for (int t = 0; t < 2; t++){
                u32 row = (u32)(warp_m + t*16 + (lane & 15));
                u32 off = row*128u + (u32)(kk*32) + (u32)((lane >> 4)*16);
                ldsm_x4(af[t], aBase + swz(off));
            }
            u32 bf[4][4];
            #pragma unroll
            for (int g = 0; g < 4; g++){
                u32 row = (u32)(warp_n + g*16 + (lane >> 4)*8 + (lane & 7));
                u32 off = row*128u + (u32)(kk*32) + (u32)(((lane >> 3) & 1)*16);
                ldsm_x4(bf[g], bBase + swz(off));
            }
            #pragma unroll
            for (int t = 0; t < 2; t++){
                #pragma unroll
                for (int g = 0; g < 4; g++){
                    mma_bf16(acc[t][g*2+0], af[t], bf[g][0], bf[g][1]);
                    mma_bf16(acc[t][g*2+1], af[t], bf[g][2], bf[g][3]);
                }
            }
        }
        __syncthreads();
    }

    // per-row xx
    #pragma unroll
    for (int i = 0; i < 8; i++){ sxx[arow0 + i*16][acol4] = xacc[i]; }
    __syncthreads();
    if (tid < 128){
        float s = 0.0f;
        #pragma unroll
        for (int c = 0; c < 16; c++){ s += sxx[tid][c]; }
        sxxr[tid] = s;
    }
    __syncthreads();

    // epilogue: dens in-place, row max, then w = exp(dens - dmax) as bf16 pairs
    const float ldc = g_scal[0];
    #pragma unroll
    for (int t = 0; t < 2; t++){
        int rl = warp_m + t*16 + (lane >> 2);
        float bias0 = ldc - 0.5f * sxxr[rl];
        float bias1 = ldc - 0.5f * sxxr[rl + 8];
        float rm0 = -3.0e38f;
        float rm1 = -3.0e38f;
        #pragma unroll
        for (int j = 0; j < 8; j++){
            int n = warp_n + j*8 + (lane & 3)*2;
            float mm0 = 0.5f * g_mm[n];
            float mm1 = 0.5f * g_mm[n+1];
            acc[t][j][0] = acc[t][j][0] - mm0 + bias0;
            acc[t][j][1] = acc[t][j][1] - mm1 + bias0;
            acc[t][j][2] = acc[t][j][2] - mm0 + bias1;
            acc[t][j][3] = acc[t][j][3] - mm1 + bias1;
            rm0 = fmaxf(rm0, fmaxf(acc[t][j][0], acc[t][j][1]));
            rm1 = fmaxf(rm1, fmaxf(acc[t][j][2], acc[t][j][3]));
        }
        rm0 = fmaxf(rm0, __shfl_xor_sync(0xffffffffu, rm0, 1));
        rm0 = fmaxf(rm0, __shfl_xor_sync(0xffffffffu, rm0, 2));
        rm1 = fmaxf(rm1, __shfl_xor_sync(0xffffffffu, rm1, 1));
        rm1 = fmaxf(rm1, __shfl_xor_sync(0xffffffffu, rm1, 2));
        if ((lane & 3) == 0){
            sdm[rl][warp & 1] = rm0;
            sdm[rl + 8][warp & 1] = rm1;
        }
    }
    __syncthreads();
    #pragma unroll
    for (int t = 0; t < 2; t++){
        int rl = warp_m + t*16 + (lane >> 2);
        float dmax0 = fmaxf(sdm[rl][0],   sdm[rl][1]);
        float dmax1 = fmaxf(sdm[rl+8][0], sdm[rl+8][1]);
        #pragma unroll
        for (int j = 0; j < 8; j++){
            int p = warp_n/2 + j*4 + (lane & 3);
            g_wpk[(m0 + rl)*64 + p] =
                packbf(__expf(acc[t][j][0] - dmax0), __expf(acc[t][j][1] - dmax0));
            g_wpk[(m0 + rl + 8)*64 + p] =
                packbf(__expf(acc[t][j][2] - dmax1), __expf(acc[t][j][3] - dmax1));
        }
        if ((warp & 1) == 0 && (lane & 3) == 0){
            g_dmax[m0 + rl]     = dmax0;
            g_dmax[m0 + rl + 8] = dmax1;
        }
    }
}

// ============================ phase 2: tensor-core recursion (v3.1) ============================
// 32 CTAs x 256 threads. 16 rows/CTA, each warp owns 16 state columns.
// 1 barrier/step, lagged renormalization, masks preloaded to smem, split MMA chains.

__device__ __forceinline__ float qmax_(float v){
    v = fmaxf(v, __shfl_xor_sync(0xffffffffu, v, 1));
    v = fmaxf(v, __shfl_xor_sync(0xffffffffu, v, 2));
    return v;
}
__device__ __forceinline__ float qsum_(float v){
    v += __shfl_xor_sync(0xffffffffu, v, 1);
    v += __shfl_xor_sync(0xffffffffu, v, 2);
    return v;
}
__device__ __forceinline__ float red8max(const float* p){
    return fmaxf(fmaxf(fmaxf(p[0], p[1]), fmaxf(p[2], p[3])),
                 fmaxf(fmaxf(p[4], p[5]), fmaxf(p[6], p[7])));
}
__device__ __forceinline__ float red8sum(const float* p){
    return ((p[0] + p[1]) + (p[2] + p[3])) + ((p[4] + p[5]) + (p[6] + p[7]));
}

#define APK_STRIDE 68

__global__ void __launch_bounds__(256) forward_kernel(const float* __restrict__ masks){
    __shared__ u32   aPk[2][16*APK_STRIDE];
    __shared__ float sredY[2][16*8];
    __shared__ float sredF[16*8];
    __shared__ float smkAll[L_][16];
    __shared__ float sfrac[L_];

    const int tid  = threadIdx.x;
    const int lane = tid & 31;
    const int warp = tid >> 5;
    const int q    = lane >> 2;
    const int c2   = lane & 3;
    const int b0   = blockIdx.x * 16;
    const int p0   = warp*8 + c2;
    const int p1   = warp*8 + 4 + c2;
    const float log_pi = -4.852030263919617f; // -log(128)

    // preload ALL masks for this CTA's 16 rows + per-step fractional flags
    if (tid < L_){
        float f = 0.0f;
        #pragma unroll 4
        for (int i = 0; i < 16; i++){
            float x = masks[(size_t)tid*B_ + b0 + i];
            smkAll[tid][i] = x;
            if (x != 0.0f && x != 1.0f) f = 1.0f;
        }
        sfrac[tid] = f;
    }

    // constant transition-matrix fragments
    u32 bfr[8][2][2];
    #pragma unroll
    for (int kt = 0; kt < 8; kt++){
        #pragma unroll
        for (int n8 = 0; n8 < 2; n8++){
            int n  = warp*16 + n8*8 + q;
            int k0 = kt*16 + c2*2;
            bfr[kt][n8][0] = packbf(g_A[(k0+0)*S_ + n], g_A[(k0+1)*S_ + n]);
            bfr[kt][n8][1] = packbf(g_A[(k0+8)*S_ + n], g_A[(k0+9)*S_ + n]);
        }
    }

    float ls0, ls1;
    float ac[2][4];
    u32 wq[4];
    u32 wqn[4] = {0u, 0u, 0u, 0u};
    float dmc0, dmc1;
    float dmn0 = 0.0f, dmn1 = 0.0f;

    // ---- t = 0 ----
    {
        size_t r0 = (size_t)(b0 + q)*64;
        size_t r1 = (size_t)(b0 + q + 8)*64;
        wq[0] = g_wpk[r0 + p0];
        wq[1] = g_wpk[r1 + p0];
        wq[2] = g_wpk[r0 + p1];
        wq[3] = g_wpk[r1 + p1];
        float dm0 = g_dmax[b0 + q];
        float dm1 = g_dmax[b0 + q + 8];
        float2 v;
        v = unpackbf(wq[0]); ac[0][0] = v.x; ac[0][1] = v.y;
        v = unpackbf(wq[1]); ac[0][2] = v.x; ac[0][3] = v.y;
        v = unpackbf(wq[2]); ac[1][0] = v.x; ac[1][1] = v.y;
        v = unpackbf(wq[3]); ac[1][2] = v.x; ac[1][3] = v.y;
        ls0 = log_pi + dm0;
        ls1 = log_pi + dm1;
        // alpha0 = w (bf16 exact copy)
        aPk[0][ q   *APK_STRIDE + p0] = wq[0];
        aPk[0][(q+8)*APK_STRIDE + p0] = wq[1];
        aPk[0][ q   *APK_STRIDE + p1] = wq[2];
        aPk[0][(q+8)*APK_STRIDE + p1] = wq[3];
        float mq  = qmax_(fmaxf(fmaxf(ac[0][0], ac[0][1]), fmaxf(ac[1][0], ac[1][1])));
        float mq8 = qmax_(fmaxf(fmaxf(ac[0][2], ac[0][3]), fmaxf(ac[1][2], ac[1][3])));
        if (c2 == 0){ sredY[0][q*8 + warp] = mq; sredY[0][(q+8)*8 + warp] = mq8; }

        // prefetch t=1
        size_t n0 = (size_t)(B_ + b0 + q)*64;
        size_t n1 = (size_t)(B_ + b0 + q + 8)*64;
        wq[0] = g_wpk[n0 + p0];
        wq[1] = g_wpk[n1 + p0];
        wq[2] = g_wpk[n0 + p1];
        wq[3] = g_wpk[n1 + p1];
        dmc0 = g_dmax[B_ + b0 + q];
        dmc1 = g_dmax[B_ + b0 + q + 8];
        __syncthreads();   // aPk + smkAll + sfrac + sredY visible
    }

    for (int t = 1; t < L_; t++){
        const int cur = t & 1;
        const int prv = cur ^ 1;

        // lagged renorm factors from previous step's stored max
        float ym0 = red8max(&sredY[prv][q*8]);
        float ym1 = red8max(&sredY[prv][(q+8)*8]);
        float lg0 = __logf(ym0);
        float lg1 = __logf(ym1);
        float inv0 = __fdividef(1.0f, ym0);
        float inv1 = __fdividef(1.0f, ym1);

        // alpha fragments
        u32 af[8][4];
        #pragma unroll
        for (int kt = 0; kt < 8; kt++){
            af[kt][0] = aPk[prv][ q   *APK_STRIDE + kt*8 + c2];
            af[kt][1] = aPk[prv][(q+8)*APK_STRIDE + kt*8 + c2];
            af[kt][2] = aPk[prv][ q   *APK_STRIDE + kt*8 + 4 + c2];
            af[kt][3] = aPk[prv][(q+8)*APK_STRIDE + kt*8 + 4 + c2];
        }

        // prefetch t+1 (w and dmax only; masks already in smem)
        if (t + 1 < L_){
            size_t n0 = (size_t)((t+1)*B_ + b0 + q)*64;
            size_t n1 = (size_t)((t+1)*B_ + b0 + q + 8)*64;
            wqn[0] = g_wpk[n0 + p0];
            wqn[1] = g_wpk[n1 + p0];
            wqn[2] = g_wpk[n0 + p1];
            wqn[3] = g_wpk[n1 + p1];
            dmn0 = g_dmax[(t+1)*B_ + b0 + q];
            dmn1 = g_dmax[(t+1)*B_ + b0 + q + 8];
        }

        // y = a x A  (two independent 4-deep chains)
        float c1a[4] = {0.f, 0.f, 0.f, 0.f};
        float c1b[4] = {0.f, 0.f, 0.f, 0.f};
        float c2a[4] = {0.f, 0.f, 0.f, 0.f};
        float c2b[4] = {0.f, 0.f, 0.f, 0.f};
        #pragma unroll
        for (int kt = 0; kt < 4; kt++){
            mma_bf16(c1a, af[kt], bfr[kt][0][0], bfr[kt][0][1]);
            mma_bf16(c1b, af[kt], bfr[kt][1][0], bfr[kt][1][1]);
        }
        #pragma unroll
        for (int kt = 4; kt < 8; kt++){
            mma_bf16(c2a, af[kt], bfr[kt][0][0], bfr[kt][0][1]);
            mma_bf16(c2b, af[kt], bfr[kt][1][0], bfr[kt][1][1]);
        }

        // multiply by w
        float acc[2][4];
        {
            float2 v;
            v = unpackbf(wq[0]); acc[0][0] = (c1a[0]+c2a[0])*v.x; acc[0][1] = (c1a[1]+c2a[1])*v.y;
            v = unpackbf(wq[1]); acc[0][2] = (c1a[2]+c2a[2])*v.x; acc[0][3] = (c1a[3]+c2a[3])*v.y;
            v = unpackbf(wq[2]); acc[1][0] = (c1b[0]+c2b[0])*v.x; acc[1][1] = (c1b[1]+c2b[1])*v.y;
            v = unpackbf(wq[3]); acc[1][2] = (c1b[2]+c2b[2])*v.x; acc[1][3] = (c1b[3]+c2b[3])*v.y;
        }

        float mk0 = smkAll[t][q];
        float mk1 = smkAll[t][q+8];
        bool one0 = (mk0 == 1.0f);
        bool one1 = (mk1 == 1.0f);

        float vnew[2][4];
        #pragma unroll
        for (int n8 = 0; n8 < 2; n8++){
            vnew[n8][0] = (one0 ? acc[n8][0] : ac[n8][0]) * inv0;
            vnew[n8][1] = (one0 ? acc[n8][1] : ac[n8][1]) * inv0;
            vnew[n8][2] = (one1 ? acc[n8][2] : ac[n8][2]) * inv1;
            vnew[n8][3] = (one1 ? acc[n8][3] : ac[n8][3]) * inv1;
        }
        float ls0n = one0 ? (ls0 + dmc0 + lg0) : (ls0 + lg0);
        float ls1n = one1 ? (ls1 + dmc1 + lg1) : (ls1 + lg1);

        // fractional-mask path (block-uniform, rare)
        if (sfrac[t] != 0.0f){
            float bl[2][4];
            #pragma unroll
            for (int n8 = 0; n8 < 2; n8++){
                bl[n8][0] = mk0*(ls0 + dmc0 + __logf(fmaxf(acc[n8][0], 1e-37f)))
                          + (1.0f-mk0)*(ls0 + __logf(fmaxf(ac[n8][0], 1e-37f)));
                bl[n8][1] = mk0*(ls0 + dmc0 + __logf(fmaxf(acc[n8][1], 1e-37f)))
                          + (1.0f-mk0)*(ls0 + __logf(fmaxf(ac[n8][1], 1e-37f)));
                bl[n8][2] = mk1*(ls1 + dmc1 + __logf(fmaxf(acc[n8][2], 1e-37f)))
                          + (1.0f-mk1)*(ls1 + __logf(fmaxf(ac[n8][2], 1e-37f)));
                bl[n8][3] = mk1*(ls1 + dmc1 + __logf(fmaxf(acc[n8][3], 1e-37f)))
                          + (1.0f-mk1)*(ls1 + __logf(fmaxf(ac[n8][3], 1e-37f)));
            }
            float bq  = qmax_(fmaxf(fmaxf(bl[0][0], bl[0][1]), fmaxf(bl[1][0], bl[1][1])));
            float bq8 = qmax_(fmaxf(fmaxf(bl[0][2], bl[0][3]), fmaxf(bl[1][2], bl[1][3])));
            if (c2 == 0){ sredF[q*8 + warp] = bq; sredF[(q+8)*8 + warp] = bq8; }
            __syncthreads();
            float bmax0 = red8max(&sredF[q*8]);
            float bmax1 = red8max(&sredF[(q+8)*8]);
            bool fr0 = (mk0 != 0.0f) && (mk0 != 1.0f);
            bool fr1 = (mk1 != 0.0f) && (mk1 != 1.0f);
            #pragma unroll
            for (int n8 = 0; n8 < 2; n8++){
                if (fr0){
                    vnew[n8][0] = __expf(bl[n8][0] - bmax0);
                    vnew[n8][1] = __expf(bl[n8][1] - bmax0);
                }
                if (fr1){
                    vnew[n8][2] = __expf(bl[n8][2] - bmax1);
                    vnew[n8][3] = __expf(bl[n8][3] - bmax1);
                }
            }
            if (fr0) ls0n = bmax0;
            if (fr1) ls1n = bmax1;
        }

        // commit
        aPk[cur][ q   *APK_STRIDE + p0] = packbf(vnew[0][0], vnew[0][1]);
        aPk[cur][(q+8)*APK_STRIDE + p0] = packbf(vnew[0][2], vnew[0][3]);
        aPk[cur][ q   *APK_STRIDE + p1] = packbf(vnew[1][0], vnew[1][1]);
        aPk[cur][(q+8)*APK_STRIDE + p1] = packbf(vnew[1][2], vnew[1][3]);
        float mq  = qmax_(fmaxf(fmaxf(vnew[0][0], vnew[0][1]), fmaxf(vnew[1][0], vnew[1][1])));
        float mq8 = qmax_(fmaxf(fmaxf(vnew[0][2], vnew[0][3]), fmaxf(vnew[1][2], vnew[1][3])));
        if (c2 == 0){ sredY[cur][q*8 + warp] = mq; sredY[cur][(q+8)*8 + warp] = mq8; }

        #pragma unroll
        for (int n8 = 0; n8 < 2; n8++){
            #pragma unroll
            for (int c = 0; c < 4; c++){ ac[n8][c] = vnew[n8][c]; }
        }
        ls0 = ls0n;
        ls1 = ls1n;
        wq[0] = wqn[0]; wq[1] = wqn[1]; wq[2] = wqn[2]; wq[3] = wqn[3];
        dmc0 = dmn0;
        dmc1 = dmn1;
        __syncthreads();
    }

    // objective: ls + log(sum_n alpha)
    {
        float sq  = qsum_((ac[0][0] + ac[0][1]) + (ac[1][0] + ac[1][1]));
        float sq8 = qsum_((ac[0][2] + ac[0][3]) + (ac[1][2] + ac[1][3]));
        if (c2 == 0){ sredF[q*8 + warp] = sq; sredF[(q+8)*8 + warp] = sq8; }
        __syncthreads();
        if (warp == 0 && c2 == 0){
            float s0 = red8sum(&sredF[q*8]);
            float s1 = red8sum(&sredF[(q+8)*8]);
            g_rowobj[b0 + q]     = ls0 + logf(s0);
            g_rowobj[b0 + q + 8] = ls1 + logf(s1);
        }
    }
}

// deterministic final reduction
__global__ void finalize_kernel(float* __restrict__ out, int out_size){
    __shared__ float sred[512];
    int t = threadIdx.x;
    sred[t] = g_rowobj[t];
    __syncthreads();
    for (int o = 256; o > 0; o >>= 1){
        if (t < o) sred[t] += sred[t+o];
        __syncthreads();
    }
    for (int i = t; i < out_size; i += 512){
        out[i] = (i == 0) ? sred[0] : 0.0f;
    }
}

// ============================ launch ============================

extern "C" void kernel_launch(void* const* d_in, const int* in_sizes, int n_in,
                              void* d_out, int out_size){
    const float* sents   = (const float*)d_in[0];  // (L,B,D)
    const float* masks   = (const float*)d_in[1];  // (L,B)
    const float* tparams = (const float*)d_in[2];  // (S,S)
    const float* means   = (const float*)d_in[3];  // (S,D)
    const float* var     = (const float*)d_in[4];  // (D,)

    prep_var_kernel<<<1, 512>>>(var);
    prep_A_kernel<<<S_, 128>>>(tparams);
    prep_W_kernel<<<S_, 128>>>(means);
    gemm_kernel<<<NROWS/128, 256>>>(sents);
    forward_kernel<<<B_/16, 256>>>(masks);
    finalize_kernel<<<1, 512>>>((float*)d_out, out_size);
}

// round 12
// speedup vs baseline: 4.1535x; 1.1344x over previous
#include <cuda_runtime.h>
#include <cuda_bf16.h>
#include <math.h>

typedef unsigned int u32;

#define L_ 128
#define B_ 512
#define D_ 512
#define S_ 128
#define NROWS (L_*B_)

// ---- device scratch (static: no allocation allowed) ----
__device__ __nv_bfloat16 g_Wbf[S_*D_];       // Wt[s][d] = means[s][d]/var[d] (bf16)
__device__ float g_A[S_*S_];                 // row-stochastic transition matrix
__device__ float g_mm[S_];                   // sum_d means^2/var
__device__ float g_ivar[D_];
__device__ float g_scal[1];                  // ldc
__device__ u32   g_wpk[(size_t)NROWS*64];    // w = exp(dens-dmax), bf16 pairs (16.7MB)
__device__ float g_dmax[NROWS];              // per-(t,b) row max of dens
__device__ float g_rowobj[B_];

// ============================ prep kernels ============================

__global__ void prep_var_kernel(const float* __restrict__ var){
    __shared__ float sred[512];
    int t = threadIdx.x;
    float v = var[t];
    g_ivar[t] = 1.0f / v;
    sred[t] = logf(v);
    __syncthreads();
    for (int o = 256; o > 0; o >>= 1){
        if (t < o) sred[t] += sred[t + o];
        __syncthreads();
    }
    if (t == 0){
        g_scal[0] = -(float)(D_/2) * logf(2.0f * 3.14159265358979323846f) - 0.5f * sred[0];
    }
}

// blocks 0..127: softmax rows of A; blocks 128..255: W rows + mm
__global__ void prep_AW_kernel(const float* __restrict__ tp,
                               const float* __restrict__ means){
    __shared__ float sred[128];
    int t = threadIdx.x;
    if (blockIdx.x < 128){
        int s = blockIdx.x;
        float v = tp[s*S_ + t];
        sred[t] = v;
        __syncthreads();
        for (int o = 64; o > 0; o >>= 1){
            if (t < o) sred[t] = fmaxf(sred[t], sred[t+o]);
            __syncthreads();
        }
        float mx = sred[0];
        __syncthreads();
        float e = expf(v - mx);
        sred[t] = e;
        __syncthreads();
        for (int o = 64; o > 0; o >>= 1){
            if (t < o) sred[t] += sred[t+o];
            __syncthreads();
        }
        g_A[s*S_ + t] = e / sred[0];
    } else {
        int s = blockIdx.x - 128;
        float acc = 0.0f;
        for (int d = t; d < D_; d += 128){
            float m = means[s*D_ + d];
            float w = m * g_ivar[d];
            g_Wbf[s*D_ + d] = __float2bfloat16(w);
            acc += m * w;
        }
        sred[t] = acc;
        __syncthreads();
        for (int o = 64; o > 0; o >>= 1){
            if (t < o) sred[t] += sred[t+o];
            __syncthreads();
        }
        if (t == 0) g_mm[s] = sred[0];
    }
}

// ============================ helpers ============================

__device__ __forceinline__ u32 swz(u32 off){
    return off ^ ((off >> 3) & 0x70u);
}
__device__ __forceinline__ void ldsm_x4(u32* r, u32 saddr){
    asm volatile("ldmatrix.sync.aligned.m8n8.x4.shared.b16 {%0,%1,%2,%3}, [%4];"
        : "=r"(r[0]), "=r"(r[1]), "=r"(r[2]), "=r"(r[3]) : "r"(saddr));
}
__device__ __forceinline__ void mma_bf16(float* c, const u32* a, u32 b0, u32 b1){
    asm volatile("mma.sync.aligned.m16n8k16.row.col.f32.bf16.bf16.f32 "
        "{%0,%1,%2,%3}, {%4,%5,%6,%7}, {%8,%9}, {%0,%1,%2,%3};"
        : "+f"(c[0]), "+f"(c[1]), "+f"(c[2]), "+f"(c[3])
        : "r"(a[0]), "r"(a[1]), "r"(a[2]), "r"(a[3]), "r"(b0), "r"(b1));
}
__device__ __forceinline__ u32 packbf(float x, float y){
    __nv_bfloat162 p = __floats2bfloat162_rn(x, y);
    return *(u32*)&p;
}
__device__ __forceinline__ float2 unpackbf(u32 v){
    __nv_bfloat162 p = *(__nv_bfloat162*)&v;
    float2 r;
    r.x = __low2float(p);
    r.y = __high2float(p);
    return r;
}

// ============================ phase 1: tensor-core GEMM ============================
// Produces w = exp(dens - dmax) (bf16 pairs) and dmax per row.

__global__ void __launch_bounds__(256) gemm_kernel(const float* __restrict__ X){
    __shared__ __align__(128) unsigned char smA[128*128];
    __shared__ __align__(128) unsigned char smB[128*128];
    __shared__ float sxx[128][16];
    __shared__ float sxxr[128];
    __shared__ float sdm[128][2];

    const int tid  = threadIdx.x;
    const int lane = tid & 31;
    const int warp = tid >> 5;
    const int warp_m = (warp >> 1) * 32;
    const int warp_n = (warp & 1) * 64;
    const size_t m0 = (size_t)blockIdx.x * 128;

    const u32 aBase = (u32)__cvta_generic_to_shared(smA);
    const u32 bBase = (u32)__cvta_generic_to_shared(smB);

    float acc[2][8][4];
    #pragma unroll
    for (int t = 0; t < 2; t++){
        #pragma unroll
        for (int j = 0; j < 8; j++){
            #pragma unroll
            for (int c = 0; c < 4; c++){ acc[t][j][c] = 0.0f; }
        }
    }
    float xacc[8];
    #pragma unroll
    for (int i = 0; i < 8; i++){ xacc[i] = 0.0f; }

    const int arow0 = tid >> 4;
    const int acol4 = tid & 15;
    const int brow0 = tid >> 3;
    const int bchk  = tid & 7;

    float4 xr[8];
    uint4  br[4];
    float4 ivr;

    {
        const int k0 = 0;
        ivr = *(const float4*)(g_ivar + k0 + acol4*4);
        #pragma unroll
        for (int i = 0; i < 8; i++){
            xr[i] = *(const float4*)(X + (m0 + arow0 + i*16)*D_ + k0 + acol4*4);
        }
        #pragma unroll
        for (int i = 0; i < 4; i++){
            br[i] = *(const uint4*)((const unsigned char*)g_Wbf + (size_t)(brow0 + i*32)*(D_*2) + k0*2 + bchk*16);
        }
    }

    for (int kt = 0; kt < 8; kt++){
        #pragma unroll
        for (int i = 0; i < 8; i++){
            int r = arow0 + i*16;
            float4 v = xr[i];
            xacc[i] += v.x*v.x*ivr.x + v.y*v.y*ivr.y + v.z*v.z*ivr.z + v.w*v.w*ivr.w;
            uint2 pk;
            pk.x = packbf(v.x, v.y);
            pk.y = packbf(v.z, v.w);
            u32 off = (u32)(r*128 + acol4*8);
            *(uint2*)(smA + swz(off)) = pk;
        }
        #pragma unroll
        for (int i = 0; i < 4; i++){
            int r = brow0 + i*32;
            u32 off = (u32)(r*128 + bchk*16);
            *(uint4*)(smB + swz(off)) = br[i];
        }
        __syncthreads();

        if (kt < 7){
            const int k0 = (kt + 1) * 64;
            ivr = *(const float4*)(g_ivar + k0 + acol4*4);
            #pragma unroll
            for (int i = 0; i < 8; i++){
                xr[i] = *(const float4*)(X + (m0 + arow0 + i*16)*D_ + k0 + acol4*4);
            }
            #pragma unroll
            for (int i = 0; i < 4; i++){
                br[i] = *(const uint4*)((const unsigned char*)g_Wbf + (size_t)(brow0 + i*32)*(D_*2) + k0*2 + bchk*16);
            }
        }

        #pragma unroll
        for (int kk = 0; kk < 4; kk++){
            u32 af[2][4];
            #pragma unroll
            for (int t = 0; t < 2; t++){
                u32 row = (u32)(warp_m + t*16 + (lane & 15));
                u32 off = row*128u + (u32)(kk*32) + (u32)((lane >> 4)*16);
                ldsm_x4(af[t], aBase + swz(off));
            }
            u32 bf[4][4];
            #pragma unroll
            for (int g = 0; g < 4; g++){
                u32 row = (u32)(warp_n + g*16 + (lane >> 4)*8 + (lane & 7));
                u32 off = row*128u + (u32)(kk*32) + (u32)(((lane >> 3) & 1)*16);
                ldsm_x4(bf[g], bBase + swz(off));
            }
            #pragma unroll
            for (int t = 0; t < 2; t++){
                #pragma unroll
                for (int g = 0; g < 4; g++){
                    mma_bf16(acc[t][g*2+0], af[t], bf[g][0], bf[g][1]);
                    mma_bf16(acc[t][g*2+1], af[t], bf[g][2], bf[g][3]);
                }
            }
        }
        __syncthreads();
    }

    // per-row xx
    #pragma unroll
    for (int i = 0; i < 8; i++){ sxx[arow0 + i*16][acol4] = xacc[i]; }
    __syncthreads();
    if (tid < 128){
        float s = 0.0f;
        #pragma unroll
        for (int c = 0; c < 16; c++){ s += sxx[tid][c]; }
        sxxr[tid] = s;
    }
    __syncthreads();

    // epilogue: dens in-place, row max, then w = exp(dens - dmax) as bf16 pairs
    const float ldc = g_scal[0];
    #pragma unroll
    for (int t = 0; t < 2; t++){
        int rl = warp_m + t*16 + (lane >> 2);
        float bias0 = ldc - 0.5f * sxxr[rl];
        float bias1 = ldc - 0.5f * sxxr[rl + 8];
        float rm0 = -3.0e38f;
        float rm1 = -3.0e38f;
        #pragma unroll
        for (int j = 0; j < 8; j++){
            int n = warp_n + j*8 + (lane & 3)*2;
            float mm0 = 0.5f * g_mm[n];
            float mm1 = 0.5f * g_mm[n+1];
            acc[t][j][0] = acc[t][j][0] - mm0 + bias0;
            acc[t][j][1] = acc[t][j][1] - mm1 + bias0;
            acc[t][j][2] = acc[t][j][2] - mm0 + bias1;
            acc[t][j][3] = acc[t][j][3] - mm1 + bias1;
            rm0 = fmaxf(rm0, fmaxf(acc[t][j][0], acc[t][j][1]));
            rm1 = fmaxf(rm1, fmaxf(acc[t][j][2], acc[t][j][3]));
        }
        rm0 = fmaxf(rm0, __shfl_xor_sync(0xffffffffu, rm0, 1));
        rm0 = fmaxf(rm0, __shfl_xor_sync(0xffffffffu, rm0, 2));
        rm1 = fmaxf(rm1, __shfl_xor_sync(0xffffffffu, rm1, 1));
        rm1 = fmaxf(rm1, __shfl_xor_sync(0xffffffffu, rm1, 2));
        if ((lane & 3) == 0){
            sdm[rl][warp & 1] = rm0;
            sdm[rl + 8][warp & 1] = rm1;
        }
    }
    __syncthreads();
    #pragma unroll
    for (int t = 0; t < 2; t++){
        int rl = warp_m + t*16 + (lane >> 2);
        float dmax0 = fmaxf(sdm[rl][0],   sdm[rl][1]);
        float dmax1 = fmaxf(sdm[rl+8][0], sdm[rl+8][1]);
        #pragma unroll
        for (int j = 0; j < 8; j++){
            int p = warp_n/2 + j*4 + (lane & 3);
            g_wpk[(m0 + rl)*64 + p] =
                packbf(__expf(acc[t][j][0] - dmax0), __expf(acc[t][j][1] - dmax0));
            g_wpk[(m0 + rl + 8)*64 + p] =
                packbf(__expf(acc[t][j][2] - dmax1), __expf(acc[t][j][3] - dmax1));
        }
        if ((warp & 1) == 0 && (lane & 3) == 0){
            g_dmax[m0 + rl]     = dmax0;
            g_dmax[m0 + rl + 8] = dmax1;
        }
    }
}

// ============================ phase 2: tensor-core recursion (v3.2) ============================
// 32 CTAs x 256 threads. 16 rows/CTA, each warp owns 16 state columns.
// 1 barrier/step, lagged renorm, masks in smem, distance-2 prefetch (A/B register sets).

__device__ __forceinline__ float qmax_(float v){
    v = fmaxf(v, __shfl_xor_sync(0xffffffffu, v, 1));
    v = fmaxf(v, __shfl_xor_sync(0xffffffffu, v, 2));
    return v;
}
__device__ __forceinline__ float qsum_(float v){
    v += __shfl_xor_sync(0xffffffffu, v, 1);
    v += __shfl_xor_sync(0xffffffffu, v, 2);
    return v;
}
__device__ __forceinline__ float red8max(const float* p){
    return fmaxf(fmaxf(fmaxf(p[0], p[1]), fmaxf(p[2], p[3])),
                 fmaxf(fmaxf(p[4], p[5]), fmaxf(p[6], p[7])));
}
__device__ __forceinline__ float red8sum(const float* p){
    return ((p[0] + p[1]) + (p[2] + p[3])) + ((p[4] + p[5]) + (p[6] + p[7]));
}

#define APK_STRIDE 68

__global__ void __launch_bounds__(256) forward_kernel(const float* __restrict__ masks){
    __shared__ u32   aPk[2][16*APK_STRIDE];
    __shared__ float sredY[2][16*8];
    __shared__ float sredF[16*8];
    __shared__ float smkAll[L_][16];
    __shared__ float sfrac[L_];

    const int tid  = threadIdx.x;
    const int lane = tid & 31;
    const int warp = tid >> 5;
    const int q    = lane >> 2;
    const int c2   = lane & 3;
    const int b0   = blockIdx.x * 16;
    const int p0   = warp*8 + c2;
    const int p1   = warp*8 + 4 + c2;
    const float log_pi = -4.852030263919617f; // -log(128)

    // preload ALL masks for this CTA's 16 rows + per-step fractional flags
    if (tid < L_){
        float f = 0.0f;
        #pragma unroll 4
        for (int i = 0; i < 16; i++){
            float x = masks[(size_t)tid*B_ + b0 + i];
            smkAll[tid][i] = x;
            if (x != 0.0f && x != 1.0f) f = 1.0f;
        }
        sfrac[tid] = f;
    }

    // constant transition-matrix fragments
    u32 bfr[8][2][2];
    #pragma unroll
    for (int kt = 0; kt < 8; kt++){
        #pragma unroll
        for (int n8 = 0; n8 < 2; n8++){
            int n  = warp*16 + n8*8 + q;
            int k0 = kt*16 + c2*2;
            bfr[kt][n8][0] = packbf(g_A[(k0+0)*S_ + n], g_A[(k0+1)*S_ + n]);
            bfr[kt][n8][1] = packbf(g_A[(k0+8)*S_ + n], g_A[(k0+9)*S_ + n]);
        }
    }

    float ls0, ls1;
    float ac[2][4];
    u32 wqA[4], wqB[4];
    float dmA0, dmA1, dmB0, dmB1;

    // ---- t = 0 init ----
    {
        size_t r0 = (size_t)(b0 + q)*64;
        size_t r1 = (size_t)(b0 + q + 8)*64;
        u32 w0 = g_wpk[r0 + p0];
        u32 w1 = g_wpk[r1 + p0];
        u32 w2 = g_wpk[r0 + p1];
        u32 w3 = g_wpk[r1 + p1];
        float dm0 = g_dmax[b0 + q];
        float dm1 = g_dmax[b0 + q + 8];
        float2 v;
        v = unpackbf(w0); ac[0][0] = v.x; ac[0][1] = v.y;
        v = unpackbf(w1); ac[0][2] = v.x; ac[0][3] = v.y;
        v = unpackbf(w2); ac[1][0] = v.x; ac[1][1] = v.y;
        v = unpackbf(w3); ac[1][2] = v.x; ac[1][3] = v.y;
        ls0 = log_pi + dm0;
        ls1 = log_pi + dm1;
        aPk[0][ q   *APK_STRIDE + p0] = w0;
        aPk[0][(q+8)*APK_STRIDE + p0] = w1;
        aPk[0][ q   *APK_STRIDE + p1] = w2;
        aPk[0][(q+8)*APK_STRIDE + p1] = w3;
        float mq  = qmax_(fmaxf(fmaxf(ac[0][0], ac[0][1]), fmaxf(ac[1][0], ac[1][1])));
        float mq8 = qmax_(fmaxf(fmaxf(ac[0][2], ac[0][3]), fmaxf(ac[1][2], ac[1][3])));
        if (c2 == 0){ sredY[0][q*8 + warp] = mq; sredY[0][(q+8)*8 + warp] = mq8; }

        // prologue prefetch: step 1 -> A set, step 2 -> B set
        size_t a0 = (size_t)(1*B_ + b0 + q)*64;
        size_t a1 = (size_t)(1*B_ + b0 + q + 8)*64;
        wqA[0] = g_wpk[a0 + p0];
        wqA[1] = g_wpk[a1 + p0];
        wqA[2] = g_wpk[a0 + p1];
        wqA[3] = g_wpk[a1 + p1];
        dmA0 = g_dmax[1*B_ + b0 + q];
        dmA1 = g_dmax[1*B_ + b0 + q + 8];
        size_t e0 = (size_t)(2*B_ + b0 + q)*64;
        size_t e1 = (size_t)(2*B_ + b0 + q + 8)*64;
        wqB[0] = g_wpk[e0 + p0];
        wqB[1] = g_wpk[e1 + p0];
        wqB[2] = g_wpk[e0 + p1];
        wqB[3] = g_wpk[e1 + p1];
        dmB0 = g_dmax[2*B_ + b0 + q];
        dmB1 = g_dmax[2*B_ + b0 + q + 8];
        __syncthreads();   // smkAll/sfrac + aPk[0] + sredY[0] visible
    }

    // one step; consumes WC/DC (data for step t), refills them with step t+2
    auto fwd_step = [&](int t, u32* WC, float& DC0, float& DC1){
        const int cur = t & 1;
        const int prv = cur ^ 1;

        float ym0 = red8max(&sredY[prv][q*8]);
        float ym1 = red8max(&sredY[prv][(q+8)*8]);
        float lg0 = __logf(ym0);
        float lg1 = __logf(ym1);
        float inv0 = __fdividef(1.0f, ym0);
        float inv1 = __fdividef(1.0f, ym1);

        u32 af[8][4];
        #pragma unroll
        for (int kt = 0; kt < 8; kt++){
            af[kt][0] = aPk[prv][ q   *APK_STRIDE + kt*8 + c2];
            af[kt][1] = aPk[prv][(q+8)*APK_STRIDE + kt*8 + c2];
            af[kt][2] = aPk[prv][ q   *APK_STRIDE + kt*8 + 4 + c2];
            af[kt][3] = aPk[prv][(q+8)*APK_STRIDE + kt*8 + 4 + c2];
        }

        // unpack this step's w, capture dmax, then refill WC/DC with t+2 data
        float wv[2][4];
        {
            float2 v2;
            v2 = unpackbf(WC[0]); wv[0][0] = v2.x; wv[0][1] = v2.y;
            v2 = unpackbf(WC[1]); wv[0][2] = v2.x; wv[0][3] = v2.y;
            v2 = unpackbf(WC[2]); wv[1][0] = v2.x; wv[1][1] = v2.y;
            v2 = unpackbf(WC[3]); wv[1][2] = v2.x; wv[1][3] = v2.y;
        }
        float dmc0 = DC0;
        float dmc1 = DC1;
        if (t + 2 < L_){
            size_t n0 = (size_t)((t+2)*B_ + b0 + q)*64;
            size_t n1 = (size_t)((t+2)*B_ + b0 + q + 8)*64;
            WC[0] = g_wpk[n0 + p0];
            WC[1] = g_wpk[n1 + p0];
            WC[2] = g_wpk[n0 + p1];
            WC[3] = g_wpk[n1 + p1];
            DC0 = g_dmax[(t+2)*B_ + b0 + q];
            DC1 = g_dmax[(t+2)*B_ + b0 + q + 8];
        }

        // y = a x A  (two independent 4-deep chains)
        float c1a[4] = {0.f, 0.f, 0.f, 0.f};
        float c1b[4] = {0.f, 0.f, 0.f, 0.f};
        float c2a[4] = {0.f, 0.f, 0.f, 0.f};
        float c2b[4] = {0.f, 0.f, 0.f, 0.f};
        #pragma unroll
        for (int kt = 0; kt < 4; kt++){
            mma_bf16(c1a, af[kt], bfr[kt][0][0], bfr[kt][0][1]);
            mma_bf16(c1b, af[kt], bfr[kt][1][0], bfr[kt][1][1]);
        }
        #pragma unroll
        for (int kt = 4; kt < 8; kt++){
            mma_bf16(c2a, af[kt], bfr[kt][0][0], bfr[kt][0][1]);
            mma_bf16(c2b, af[kt], bfr[kt][1][0], bfr[kt][1][1]);
        }

        float acc[2][4];
        #pragma unroll
        for (int c = 0; c < 4; c++){
            acc[0][c] = (c1a[c] + c2a[c]) * wv[0][c];
            acc[1][c] = (c1b[c] + c2b[c]) * wv[1][c];
        }

        float mk0 = smkAll[t][q];
        float mk1 = smkAll[t][q+8];
        bool one0 = (mk0 == 1.0f);
        bool one1 = (mk1 == 1.0f);

        float vnew[2][4];
        #pragma unroll
        for (int n8 = 0; n8 < 2; n8++){
            vnew[n8][0] = (one0 ? acc[n8][0] : ac[n8][0]) * inv0;
            vnew[n8][1] = (one0 ? acc[n8][1] : ac[n8][1]) * inv0;
            vnew[n8][2] = (one1 ? acc[n8][2] : ac[n8][2]) * inv1;
            vnew[n8][3] = (one1 ? acc[n8][3] : ac[n8][3]) * inv1;
        }
        float ls0n = one0 ? (ls0 + dmc0 + lg0) : (ls0 + lg0);
        float ls1n = one1 ? (ls1 + dmc1 + lg1) : (ls1 + lg1);

        // fractional-mask path (block-uniform, rare)
        if (sfrac[t] != 0.0f){
            float bl[2][4];
            #pragma unroll
            for (int n8 = 0; n8 < 2; n8++){
                bl[n8][0] = mk0*(ls0 + dmc0 + __logf(fmaxf(acc[n8][0], 1e-37f)))
                          + (1.0f-mk0)*(ls0 + __logf(fmaxf(ac[n8][0], 1e-37f)));
                bl[n8][1] = mk0*(ls0 + dmc0 + __logf(fmaxf(acc[n8][1], 1e-37f)))
                          + (1.0f-mk0)*(ls0 + __logf(fmaxf(ac[n8][1], 1e-37f)));
                bl[n8][2] = mk1*(ls1 + dmc1 + __logf(fmaxf(acc[n8][2], 1e-37f)))
                          + (1.0f-mk1)*(ls1 + __logf(fmaxf(ac[n8][2], 1e-37f)));
                bl[n8][3] = mk1*(ls1 + dmc1 + __logf(fmaxf(acc[n8][3], 1e-37f)))
                          + (1.0f-mk1)*(ls1 + __logf(fmaxf(ac[n8][3], 1e-37f)));
            }
            float bq  = qmax_(fmaxf(fmaxf(bl[0][0], bl[0][1]), fmaxf(bl[1][0], bl[1][1])));
            float bq8 = qmax_(fmaxf(fmaxf(bl[0][2], bl[0][3]), fmaxf(bl[1][2], bl[1][3])));
            if (c2 == 0){ sredF[q*8 + warp] = bq; sredF[(q+8)*8 + warp] = bq8; }
            __syncthreads();
            float bmax0 = red8max(&sredF[q*8]);
            float bmax1 = red8max(&sredF[(q+8)*8]);
            bool fr0 = (mk0 != 0.0f) && (mk0 != 1.0f);
            bool fr1 = (mk1 != 0.0f) && (mk1 != 1.0f);
            #pragma unroll
            for (int n8 = 0; n8 < 2; n8++){
                if (fr0){
                    vnew[n8][0] = __expf(bl[n8][0] - bmax0);
                    vnew[n8][1] = __expf(bl[n8][1] - bmax0);
                }
                if (fr1){
                    vnew[n8][2] = __expf(bl[n8][2] - bmax1);
                    vnew[n8][3] = __expf(bl[n8][3] - bmax1);
                }
            }
            if (fr0) ls0n = bmax0;
            if (fr1) ls1n = bmax1;
        }

        // commit
        aPk[cur][ q   *APK_STRIDE + p0] = packbf(vnew[0][0], vnew[0][1]);
        aPk[cur][(q+8)*APK_STRIDE + p0] = packbf(vnew[0][2], vnew[0][3]);
        aPk[cur][ q   *APK_STRIDE + p1] = packbf(vnew[1][0], vnew[1][1]);
        aPk[cur][(q+8)*APK_STRIDE + p1] = packbf(vnew[1][2], vnew[1][3]);
        float mq  = qmax_(fmaxf(fmaxf(vnew[0][0], vnew[0][1]), fmaxf(vnew[1][0], vnew[1][1])));
        float mq8 = qmax_(fmaxf(fmaxf(vnew[0][2], vnew[0][3]), fmaxf(vnew[1][2], vnew[1][3])));
        if (c2 == 0){ sredY[cur][q*8 + warp] = mq; sredY[cur][(q+8)*8 + warp] = mq8; }

        #pragma unroll
        for (int n8 = 0; n8 < 2; n8++){
            #pragma unroll
            for (int c = 0; c < 4; c++){ ac[n8][c] = vnew[n8][c]; }
        }
        ls0 = ls0n;
        ls1 = ls1n;
        __syncthreads();
    };

    // main loop: odd steps consume set A, even steps set B (distance-2 prefetch)
    int t = 1;
    for (; t + 1 < L_; t += 2){
        fwd_step(t,     wqA, dmA0, dmA1);
        fwd_step(t + 1, wqB, dmB0, dmB1);
    }
    if (t < L_){
        fwd_step(t, wqA, dmA0, dmA1);
    }

    // objective: ls + log(sum_n alpha)
    {
        float sq  = qsum_((ac[0][0] + ac[0][1]) + (ac[1][0] + ac[1][1]));
        float sq8 = qsum_((ac[0][2] + ac[0][3]) + (ac[1][2] + ac[1][3]));
        if (c2 == 0){ sredF[q*8 + warp] = sq; sredF[(q+8)*8 + warp] = sq8; }
        __syncthreads();
        if (warp == 0 && c2 == 0){
            float s0 = red8sum(&sredF[q*8]);
            float s1 = red8sum(&sredF[(q+8)*8]);
            g_rowobj[b0 + q]     = ls0 + logf(s0);
            g_rowobj[b0 + q + 8] = ls1 + logf(s1);
        }
    }
}

// deterministic final reduction
__global__ void finalize_kernel(float* __restrict__ out, int out_size){
    __shared__ float sred[512];
    int t = threadIdx.x;
    sred[t] = g_rowobj[t];
    __syncthreads();
    for (int o = 256; o > 0; o >>= 1){
        if (t < o) sred[t] += sred[t+o];
        __syncthreads();
    }
    for (int i = t; i < out_size; i += 512){
        out[i] = (i == 0) ? sred[0] : 0.0f;
    }
}

// ============================ launch ============================

extern "C" void kernel_launch(void* const* d_in, const int* in_sizes, int n_in,
                              void* d_out, int out_size){
    const float* sents   = (const float*)d_in[0];  // (L,B,D)
    const float* masks   = (const float*)d_in[1];  // (L,B)
    const float* tparams = (const float*)d_in[2];  // (S,S)
    const float* means   = (const float*)d_in[3];  // (S,D)
    const float* var     = (const float*)d_in[4];  // (D,)

    prep_var_kernel<<<1, 512>>>(var);
    prep_AW_kernel<<<256, 128>>>(tparams, means);
    gemm_kernel<<<NROWS/128, 256>>>(sents);
    forward_kernel<<<B_/16, 256>>>(masks);
    finalize_kernel<<<1, 512>>>((float*)d_out, out_size);
}

// round 14
// speedup vs baseline: 4.7199x; 1.1364x over previous
#include <cuda_runtime.h>
#include <cuda_bf16.h>
#include <math.h>

typedef unsigned int u32;

#define L_ 128
#define B_ 512
#define D_ 512
#define S_ 128
#define NROWS (L_*B_)

// ---- device scratch (static: no allocation allowed) ----
__device__ __nv_bfloat16 g_Wbf[S_*D_];       // Wt[s][d] = means[s][d]/var[d] (bf16)
__device__ float g_A[S_*S_];                 // row-stochastic transition matrix
__device__ float g_mm[S_];                   // sum_d means^2/var
__device__ float g_ivar[D_];
__device__ float g_scal[1];                  // ldc
__device__ u32   g_wpk[(size_t)NROWS*64];    // w = exp(dens-dmax), bf16 pairs (16.7MB)
__device__ float g_dmax[NROWS];              // per-(t,b) row max of dens
__device__ float g_rowobj[B_];

// ============================ prep kernels ============================

__global__ void prep_var_kernel(const float* __restrict__ var){
    __shared__ float sred[512];
    int t = threadIdx.x;
    float v = var[t];
    g_ivar[t] = 1.0f / v;
    sred[t] = logf(v);
    __syncthreads();
    for (int o = 256; o > 0; o >>= 1){
        if (t < o) sred[t] += sred[t + o];
        __syncthreads();
    }
    if (t == 0){
        g_scal[0] = -(float)(D_/2) * logf(2.0f * 3.14159265358979323846f) - 0.5f * sred[0];
    }
}

// blocks 0..127: softmax rows of A; blocks 128..255: W rows + mm
__global__ void prep_AW_kernel(const float* __restrict__ tp,
                               const float* __restrict__ means){
    __shared__ float sred[128];
    int t = threadIdx.x;
    if (blockIdx.x < 128){
        int s = blockIdx.x;
        float v = tp[s*S_ + t];
        sred[t] = v;
        __syncthreads();
        for (int o = 64; o > 0; o >>= 1){
            if (t < o) sred[t] = fmaxf(sred[t], sred[t+o]);
            __syncthreads();
        }
        float mx = sred[0];
        __syncthreads();
        float e = expf(v - mx);
        sred[t] = e;
        __syncthreads();
        for (int o = 64; o > 0; o >>= 1){
            if (t < o) sred[t] += sred[t+o];
            __syncthreads();
        }
        g_A[s*S_ + t] = e / sred[0];
    } else {
        int s = blockIdx.x - 128;
        float acc = 0.0f;
        for (int d = t; d < D_; d += 128){
            float m = means[s*D_ + d];
            float w = m * g_ivar[d];
            g_Wbf[s*D_ + d] = __float2bfloat16(w);
            acc += m * w;
        }
        sred[t] = acc;
        __syncthreads();
        for (int o = 64; o > 0; o >>= 1){
            if (t < o) sred[t] += sred[t+o];
            __syncthreads();
        }
        if (t == 0) g_mm[s] = sred[0];
    }
}

// ============================ helpers ============================

__device__ __forceinline__ u32 swz(u32 off){
    return off ^ ((off >> 3) & 0x70u);
}
__device__ __forceinline__ void ldsm_x4(u32* r, u32 saddr){
    asm volatile("ldmatrix.sync.aligned.m8n8.x4.shared.b16 {%0,%1,%2,%3}, [%4];"
        : "=r"(r[0]), "=r"(r[1]), "=r"(r[2]), "=r"(r[3]) : "r"(saddr));
}
__device__ __forceinline__ void mma_bf16(float* c, const u32* a, u32 b0, u32 b1){
    asm volatile("mma.sync.aligned.m16n8k16.row.col.f32.bf16.bf16.f32 "
        "{%0,%1,%2,%3}, {%4,%5,%6,%7}, {%8,%9}, {%0,%1,%2,%3};"
        : "+f"(c[0]), "+f"(c[1]), "+f"(c[2]), "+f"(c[3])
        : "r"(a[0]), "r"(a[1]), "r"(a[2]), "r"(a[3]), "r"(b0), "r"(b1));
}
__device__ __forceinline__ u32 packbf(float x, float y){
    __nv_bfloat162 p = __floats2bfloat162_rn(x, y);
    return *(u32*)&p;
}
__device__ __forceinline__ float2 unpackbf(u32 v){
    __nv_bfloat162 p = *(__nv_bfloat162*)&v;
    float2 r;
    r.x = __low2float(p);
    r.y = __high2float(p);
    return r;
}

// ============================ phase 1: tensor-core GEMM ============================
// Produces w = exp(dens - dmax) (bf16 pairs) and dmax per row.

__global__ void __launch_bounds__(256) gemm_kernel(const float* __restrict__ X){
    __shared__ __align__(128) unsigned char smA[128*128];
    __shared__ __align__(128) unsigned char smB[128*128];
    __shared__ float sxx[128][16];
    __shared__ float sxxr[128];
    __shared__ float sdm[128][2];

    const int tid  = threadIdx.x;
    const int lane = tid & 31;
    const int warp = tid >> 5;
    const int warp_m = (warp >> 1) * 32;
    const int warp_n = (warp & 1) * 64;
    const size_t m0 = (size_t)blockIdx.x * 128;

    const u32 aBase = (u32)__cvta_generic_to_shared(smA);
    const u32 bBase = (u32)__cvta_generic_to_shared(smB);

    float acc[2][8][4];
    #pragma unroll
    for (int t = 0; t < 2; t++){
        #pragma unroll
        for (int j = 0; j < 8; j++){
            #pragma unroll
            for (int c = 0; c < 4; c++){ acc[t][j][c] = 0.0f; }
        }
    }
    float xacc[8];
    #pragma unroll
    for (int i = 0; i < 8; i++){ xacc[i] = 0.0f; }

    const int arow0 = tid >> 4;
    const int acol4 = tid & 15;
    const int brow0 = tid >> 3;
    const int bchk  = tid & 7;

    float4 xr[8];
    uint4  br[4];
    float4 ivr;

    {
        const int k0 = 0;
        ivr = *(const float4*)(g_ivar + k0 + acol4*4);
        #pragma unroll
        for (int i = 0; i < 8; i++){
            xr[i] = *(const float4*)(X + (m0 + arow0 + i*16)*D_ + k0 + acol4*4);
        }
        #pragma unroll
        for (int i = 0; i < 4; i++){
            br[i] = *(const uint4*)((const unsigned char*)g_Wbf + (size_t)(brow0 + i*32)*(D_*2) + k0*2 + bchk*16);
        }
    }

    for (int kt = 0; kt < 8; kt++){
        #pragma unroll
        for (int i = 0; i < 8; i++){
            int r = arow0 + i*16;
            float4 v = xr[i];
            xacc[i] += v.x*v.x*ivr.x + v.y*v.y*ivr.y + v.z*v.z*ivr.z + v.w*v.w*ivr.w;
            uint2 pk;
            pk.x = packbf(v.x, v.y);
            pk.y = packbf(v.z, v.w);
            u32 off = (u32)(r*128 + acol4*8);
            *(uint2*)(smA + swz(off)) = pk;
        }
        #pragma unroll
        for (int i = 0; i < 4; i++){
            int r = brow0 + i*32;
            u32 off = (u32)(r*128 + bchk*16);
            *(uint4*)(smB + swz(off)) = br[i];
        }
        __syncthreads();

        if (kt < 7){
            const int k0 = (kt + 1) * 64;
            ivr = *(const float4*)(g_ivar + k0 + acol4*4);
            #pragma unroll
            for (int i = 0; i < 8; i++){
                xr[i] = *(const float4*)(X + (m0 + arow0 + i*16)*D_ + k0 + acol4*4);
            }
            #pragma unroll
            for (int i = 0; i < 4; i++){
                br[i] = *(const uint4*)((const unsigned char*)g_Wbf + (size_t)(brow0 + i*32)*(D_*2) + k0*2 + bchk*16);
            }
        }

        #pragma unroll
        for (int kk = 0; kk < 4; kk++){
            u32 af[2][4];
            #pragma unroll
            for (int t = 0; t < 2; t++){
                u32 row = (u32)(warp_m + t*16 + (lane & 15));
                u32 off = row*128u + (u32)(kk*32) + (u32)((lane >> 4)*16);
                ldsm_x4(af[t], aBase + swz(off));
            }
            u32 bf[4][4];
            #pragma unroll
            for (int g = 0; g < 4; g++){
                u32 row = (u32)(warp_n + g*16 + (lane >> 4)*8 + (lane & 7));
                u32 off = row*128u + (u32)(kk*32) + (u32)(((lane >> 3) & 1)*16);
                ldsm_x4(bf[g], bBase + swz(off));
            }
            #pragma unroll
            for (int t = 0; t < 2; t++){
                #pragma unroll
                for (int g = 0; g < 4; g++){
                    mma_bf16(acc[t][g*2+0], af[t], bf[g][0], bf[g][1]);
                    mma_bf16(acc[t][g*2+1], af[t], bf[g][2], bf[g][3]);
                }
            }
        }
        __syncthreads();
    }

    // per-row xx
    #pragma unroll
    for (int i = 0; i < 8; i++){ sxx[arow0 + i*16][acol4] = xacc[i]; }
    __syncthreads();
    if (tid < 128){
        float s = 0.0f;
        #pragma unroll
        for (int c = 0; c < 16; c++){ s += sxx[tid][c]; }
        sxxr[tid] = s;
    }
    __syncthreads();

    // epilogue: dens in-place, row max, then w = exp(dens - dmax) as bf16 pairs
    const float ldc = g_scal[0];
    #pragma unroll
    for (int t = 0; t < 2; t++){
        int rl = warp_m + t*16 + (lane >> 2);
        float bias0 = ldc - 0.5f * sxxr[rl];
        float bias1 = ldc - 0.5f * sxxr[rl + 8];
        float rm0 = -3.0e38f;
        float rm1 = -3.0e38f;
        #pragma unroll
        for (int j = 0; j < 8; j++){
            int n = warp_n + j*8 + (lane & 3)*2;
            float mm0 = 0.5f * g_mm[n];
            float mm1 = 0.5f * g_mm[n+1];
            acc[t][j][0] = acc[t][j][0] - mm0 + bias0;
            acc[t][j][1] = acc[t][j][1] - mm1 + bias0;
            acc[t][j][2] = acc[t][j][2] - mm0 + bias1;
            acc[t][j][3] = acc[t][j][3] - mm1 + bias1;
            rm0 = fmaxf(rm0, fmaxf(acc[t][j][0], acc[t][j][1]));
            rm1 = fmaxf(rm1, fmaxf(acc[t][j][2], acc[t][j][3]));
        }
        rm0 = fmaxf(rm0, __shfl_xor_sync(0xffffffffu, rm0, 1));
        rm0 = fmaxf(rm0, __shfl_xor_sync(0xffffffffu, rm0, 2));
        rm1 = fmaxf(rm1, __shfl_xor_sync(0xffffffffu, rm1, 1));
        rm1 = fmaxf(rm1, __shfl_xor_sync(0xffffffffu, rm1, 2));
        if ((lane & 3) == 0){
            sdm[rl][warp & 1] = rm0;
            sdm[rl + 8][warp & 1] = rm1;
        }
    }
    __syncthreads();
    #pragma unroll
    for (int t = 0; t < 2; t++){
        int rl = warp_m + t*16 + (lane >> 2);
        float dmax0 = fmaxf(sdm[rl][0],   sdm[rl][1]);
        float dmax1 = fmaxf(sdm[rl+8][0], sdm[rl+8][1]);
        #pragma unroll
        for (int j = 0; j < 8; j++){
            int p = warp_n/2 + j*4 + (lane & 3);
            g_wpk[(m0 + rl)*64 + p] =
                packbf(__expf(acc[t][j][0] - dmax0), __expf(acc[t][j][1] - dmax0));
            g_wpk[(m0 + rl + 8)*64 + p] =
                packbf(__expf(acc[t][j][2] - dmax1), __expf(acc[t][j][3] - dmax1));
        }
        if ((warp & 1) == 0 && (lane & 3) == 0){
            g_dmax[m0 + rl]     = dmax0;
            g_dmax[m0 + rl + 8] = dmax1;
        }
    }
}

// ============================ phase 2: tensor-core recursion (v5) ============================
// 32 CTAs x 128 threads (4 warps). 16 rows/CTA, each warp owns 32 state columns
// (4 n8-tiles). 1 four-warp barrier/step, lagged renorm, masks in smem,
// distance-2 prefetch (A/B register sets), 8 independent 4-deep MMA chains.

__device__ __forceinline__ float qmax_(float v){
    v = fmaxf(v, __shfl_xor_sync(0xffffffffu, v, 1));
    v = fmaxf(v, __shfl_xor_sync(0xffffffffu, v, 2));
    return v;
}
__device__ __forceinline__ float qsum_(float v){
    v += __shfl_xor_sync(0xffffffffu, v, 1);
    v += __shfl_xor_sync(0xffffffffu, v, 2);
    return v;
}
__device__ __forceinline__ float red4max(const float* p){
    return fmaxf(fmaxf(p[0], p[1]), fmaxf(p[2], p[3]));
}
__device__ __forceinline__ float red4sum(const float* p){
    return (p[0] + p[1]) + (p[2] + p[3]);
}

#define APK_STRIDE 68

__global__ void __launch_bounds__(128) forward_kernel(const float* __restrict__ masks){
    __shared__ u32   aPk[2][16*APK_STRIDE];
    __shared__ float sredY[2][16*4];
    __shared__ float sredF[16*4];
    __shared__ float smkAll[L_][16];
    __shared__ float sfrac[L_];

    const int tid  = threadIdx.x;
    const int lane = tid & 31;
    const int warp = tid >> 5;          // 0..3
    const int q    = lane >> 2;         // 0..7
    const int c2   = lane & 3;          // 0..3
    const int b0   = blockIdx.x * 16;
    const float log_pi = -4.852030263919617f; // -log(128)

    // w-pair indices for this thread's 4 tiles (J = warp*4 + jj), cols J*8 + c2*2
    int pidx[4];
    #pragma unroll
    for (int jj = 0; jj < 4; jj++){ pidx[jj] = warp*16 + jj*4 + c2; }

    // preload ALL masks for this CTA's 16 rows + per-step fractional flags
    {
        float f = 0.0f;
        #pragma unroll 4
        for (int i = 0; i < 16; i++){
            float x = masks[(size_t)tid*B_ + b0 + i];
            smkAll[tid][i] = x;
            if (x != 0.0f && x != 1.0f) f = 1.0f;
        }
        sfrac[tid] = f;
    }

    // constant transition-matrix fragments: B operand for tiles J = warp*4 + jj
    u32 bfr[8][4][2];
    #pragma unroll
    for (int kt = 0; kt < 8; kt++){
        #pragma unroll
        for (int jj = 0; jj < 4; jj++){
            int n  = warp*32 + jj*8 + q;
            int k0 = kt*16 + c2*2;
            bfr[kt][jj][0] = packbf(g_A[(k0+0)*S_ + n], g_A[(k0+1)*S_ + n]);
            bfr[kt][jj][1] = packbf(g_A[(k0+8)*S_ + n], g_A[(k0+9)*S_ + n]);
        }
    }

    float ls0, ls1;
    float ac[4][4];           // [jj][c]: c0,c1 = row q cols pair; c2,c3 = row q+8
    u32 wqA[8], wqB[8];       // [jj*2+0] = row q pair, [jj*2+1] = row q+8 pair
    float dmA0, dmA1, dmB0, dmB1;

    // ---- t = 0 init ----
    {
        size_t r0 = (size_t)(b0 + q)*64;
        size_t r1 = (size_t)(b0 + q + 8)*64;
        u32 w0[8];
        #pragma unroll
        for (int jj = 0; jj < 4; jj++){
            w0[jj*2+0] = g_wpk[r0 + pidx[jj]];
            w0[jj*2+1] = g_wpk[r1 + pidx[jj]];
        }
        float dm0 = g_dmax[b0 + q];
        float dm1 = g_dmax[b0 + q + 8];
        #pragma unroll
        for (int jj = 0; jj < 4; jj++){
            float2 v;
            v = unpackbf(w0[jj*2+0]); ac[jj][0] = v.x; ac[jj][1] = v.y;
            v = unpackbf(w0[jj*2+1]); ac[jj][2] = v.x; ac[jj][3] = v.y;
        }
        ls0 = log_pi + dm0;
        ls1 = log_pi + dm1;
        // alpha0 = w (bf16 exact copy) into fragment-direct layout
        #pragma unroll
        for (int jj = 0; jj < 4; jj++){
            int J = warp*4 + jj;
            aPk[0][ q   *APK_STRIDE + J*4 + c2] = w0[jj*2+0];
            aPk[0][(q+8)*APK_STRIDE + J*4 + c2] = w0[jj*2+1];
        }
        float mq  = fmaxf(fmaxf(fmaxf(ac[0][0], ac[0][1]), fmaxf(ac[1][0], ac[1][1])),
                          fmaxf(fmaxf(ac[2][0], ac[2][1]), fmaxf(ac[3][0], ac[3][1])));
        float mq8 = fmaxf(fmaxf(fmaxf(ac[0][2], ac[0][3]), fmaxf(ac[1][2], ac[1][3])),
                          fmaxf(fmaxf(ac[2][2], ac[2][3]), fmaxf(ac[3][2], ac[3][3])));
        mq = qmax_(mq); mq8 = qmax_(mq8);
        if (c2 == 0){ sredY[0][q*4 + warp] = mq; sredY[0][(q+8)*4 + warp] = mq8; }

        // prologue prefetch: step 1 -> A set, step 2 -> B set
        size_t a0 = (size_t)(1*B_ + b0 + q)*64;
        size_t a1 = (size_t)(1*B_ + b0 + q + 8)*64;
        #pragma unroll
        for (int jj = 0; jj < 4; jj++){
            wqA[jj*2+0] = g_wpk[a0 + pidx[jj]];
            wqA[jj*2+1] = g_wpk[a1 + pidx[jj]];
        }
        dmA0 = g_dmax[1*B_ + b0 + q];
        dmA1 = g_dmax[1*B_ + b0 + q + 8];
        size_t e0 = (size_t)(2*B_ + b0 + q)*64;
        size_t e1 = (size_t)(2*B_ + b0 + q + 8)*64;
        #pragma unroll
        for (int jj = 0; jj < 4; jj++){
            wqB[jj*2+0] = g_wpk[e0 + pidx[jj]];
            wqB[jj*2+1] = g_wpk[e1 + pidx[jj]];
        }
        dmB0 = g_dmax[2*B_ + b0 + q];
        dmB1 = g_dmax[2*B_ + b0 + q + 8];
        __syncthreads();   // smkAll/sfrac + aPk[0] + sredY[0] visible
    }

    // one step; consumes WC/DC (data for step t), refills with step t+2
    auto fwd_step = [&](int t, u32* WC, float& DC0, float& DC1){
        const int cur = t & 1;
        const int prv = cur ^ 1;

        float ym0 = red4max(&sredY[prv][q*4]);
        float ym1 = red4max(&sredY[prv][(q+8)*4]);
        float lg0 = __logf(ym0);
        float lg1 = __logf(ym1);
        float inv0 = __fdividef(1.0f, ym0);
        float inv1 = __fdividef(1.0f, ym1);

        u32 af[8][4];
        #pragma unroll
        for (int kt = 0; kt < 8; kt++){
            af[kt][0] = aPk[prv][ q   *APK_STRIDE + kt*8 + c2];
            af[kt][1] = aPk[prv][(q+8)*APK_STRIDE + kt*8 + c2];
            af[kt][2] = aPk[prv][ q   *APK_STRIDE + kt*8 + 4 + c2];
            af[kt][3] = aPk[prv][(q+8)*APK_STRIDE + kt*8 + 4 + c2];
        }

        // unpack this step's w, capture dmax, then refill WC/DC with t+2 data
        float wv[4][4];
        #pragma unroll
        for (int jj = 0; jj < 4; jj++){
            float2 v2;
            v2 = unpackbf(WC[jj*2+0]); wv[jj][0] = v2.x; wv[jj][1] = v2.y;
            v2 = unpackbf(WC[jj*2+1]); wv[jj][2] = v2.x; wv[jj][3] = v2.y;
        }
        float dmc0 = DC0;
        float dmc1 = DC1;
        if (t + 2 < L_){
            size_t n0 = (size_t)((t+2)*B_ + b0 + q)*64;
            size_t n1 = (size_t)((t+2)*B_ + b0 + q + 8)*64;
            #pragma unroll
            for (int jj = 0; jj < 4; jj++){
                WC[jj*2+0] = g_wpk[n0 + pidx[jj]];
                WC[jj*2+1] = g_wpk[n1 + pidx[jj]];
            }
            DC0 = g_dmax[(t+2)*B_ + b0 + q];
            DC1 = g_dmax[(t+2)*B_ + b0 + q + 8];
        }

        // y = a x A : 8 independent 4-deep chains (x1 = kt 0..3, x2 = kt 4..7)
        float x1[4][4];
        float x2[4][4];
        #pragma unroll
        for (int jj = 0; jj < 4; jj++){
            #pragma unroll
            for (int c = 0; c < 4; c++){ x1[jj][c] = 0.0f; x2[jj][c] = 0.0f; }
        }
        #pragma unroll
        for (int kt = 0; kt < 4; kt++){
            #pragma unroll
            for (int jj = 0; jj < 4; jj++){
                mma_bf16(x1[jj], af[kt], bfr[kt][jj][0], bfr[kt][jj][1]);
            }
        }
        #pragma unroll
        for (int kt = 4; kt < 8; kt++){
            #pragma unroll
            for (int jj = 0; jj < 4; jj++){
                mma_bf16(x2[jj], af[kt], bfr[kt][jj][0], bfr[kt][jj][1]);
            }
        }

        float acc[4][4];
        #pragma unroll
        for (int jj = 0; jj < 4; jj++){
            #pragma unroll
            for (int c = 0; c < 4; c++){
                acc[jj][c] = (x1[jj][c] + x2[jj][c]) * wv[jj][c];
            }
        }

        float mk0 = smkAll[t][q];
        float mk1 = smkAll[t][q+8];
        bool one0 = (mk0 == 1.0f);
        bool one1 = (mk1 == 1.0f);

        float vnew[4][4];
        #pragma unroll
        for (int jj = 0; jj < 4; jj++){
            vnew[jj][0] = (one0 ? acc[jj][0] : ac[jj][0]) * inv0;
            vnew[jj][1] = (one0 ? acc[jj][1] : ac[jj][1]) * inv0;
            vnew[jj][2] = (one1 ? acc[jj][2] : ac[jj][2]) * inv1;
            vnew[jj][3] = (one1 ? acc[jj][3] : ac[jj][3]) * inv1;
        }
        float ls0n = one0 ? (ls0 + dmc0 + lg0) : (ls0 + lg0);
        float ls1n = one1 ? (ls1 + dmc1 + lg1) : (ls1 + lg1);

        // fractional-mask path (block-uniform, rare)
        if (sfrac[t] != 0.0f){
            float bl[4][4];
            #pragma unroll
            for (int jj = 0; jj < 4; jj++){
                bl[jj][0] = mk0*(ls0 + dmc0 + __logf(fmaxf(acc[jj][0], 1e-37f)))
                          + (1.0f-mk0)*(ls0 + __logf(fmaxf(ac[jj][0], 1e-37f)));
                bl[jj][1] = mk0*(ls0 + dmc0 + __logf(fmaxf(acc[jj][1], 1e-37f)))
                          + (1.0f-mk0)*(ls0 + __logf(fmaxf(ac[jj][1], 1e-37f)));
                bl[jj][2] = mk1*(ls1 + dmc1 + __logf(fmaxf(acc[jj][2], 1e-37f)))
                          + (1.0f-mk1)*(ls1 + __logf(fmaxf(ac[jj][2], 1e-37f)));
                bl[jj][3] = mk1*(ls1 + dmc1 + __logf(fmaxf(acc[jj][3], 1e-37f)))
                          + (1.0f-mk1)*(ls1 + __logf(fmaxf(ac[jj][3], 1e-37f)));
            }
            float bq  = fmaxf(fmaxf(fmaxf(bl[0][0], bl[0][1]), fmaxf(bl[1][0], bl[1][1])),
                              fmaxf(fmaxf(bl[2][0], bl[2][1]), fmaxf(bl[3][0], bl[3][1])));
            float bq8 = fmaxf(fmaxf(fmaxf(bl[0][2], bl[0][3]), fmaxf(bl[1][2], bl[1][3])),
                              fmaxf(fmaxf(bl[2][2], bl[2][3]), fmaxf(bl[3][2], bl[3][3])));
            bq = qmax_(bq); bq8 = qmax_(bq8);
            if (c2 == 0){ sredF[q*4 + warp] = bq; sredF[(q+8)*4 + warp] = bq8; }
            __syncthreads();
            float bmax0 = red4max(&sredF[q*4]);
            float bmax1 = red4max(&sredF[(q+8)*4]);
            bool fr0 = (mk0 != 0.0f) && (mk0 != 1.0f);
            bool fr1 = (mk1 != 0.0f) && (mk1 != 1.0f);
            #pragma unroll
            for (int jj = 0; jj < 4; jj++){
                if (fr0){
                    vnew[jj][0] = __expf(bl[jj][0] - bmax0);
                    vnew[jj][1] = __expf(bl[jj][1] - bmax0);
                }
                if (fr1){
                    vnew[jj][2] = __expf(bl[jj][2] - bmax1);
                    vnew[jj][3] = __expf(bl[jj][3] - bmax1);
                }
            }
            if (fr0) ls0n = bmax0;
            if (fr1) ls1n = bmax1;
        }

        // commit (fragment-direct layout, conflict-free)
        #pragma unroll
        for (int jj = 0; jj < 4; jj++){
            int J = warp*4 + jj;
            aPk[cur][ q   *APK_STRIDE + J*4 + c2] = packbf(vnew[jj][0], vnew[jj][1]);
            aPk[cur][(q+8)*APK_STRIDE + J*4 + c2] = packbf(vnew[jj][2], vnew[jj][3]);
        }
        float mq  = fmaxf(fmaxf(fmaxf(vnew[0][0], vnew[0][1]), fmaxf(vnew[1][0], vnew[1][1])),
                          fmaxf(fmaxf(vnew[2][0], vnew[2][1]), fmaxf(vnew[3][0], vnew[3][1])));
        float mq8 = fmaxf(fmaxf(fmaxf(vnew[0][2], vnew[0][3]), fmaxf(vnew[1][2], vnew[1][3])),
                          fmaxf(fmaxf(vnew[2][2], vnew[2][3]), fmaxf(vnew[3][2], vnew[3][3])));
        mq = qmax_(mq); mq8 = qmax_(mq8);
        if (c2 == 0){ sredY[cur][q*4 + warp] = mq; sredY[cur][(q+8)*4 + warp] = mq8; }

        #pragma unroll
        for (int jj = 0; jj < 4; jj++){
            #pragma unroll
            for (int c = 0; c < 4; c++){ ac[jj][c] = vnew[jj][c]; }
        }
        ls0 = ls0n;
        ls1 = ls1n;
        __syncthreads();
    };

    // main loop: odd steps consume set A, even steps set B (distance-2 prefetch)
    int t = 1;
    for (; t + 1 < L_; t += 2){
        fwd_step(t,     wqA, dmA0, dmA1);
        fwd_step(t + 1, wqB, dmB0, dmB1);
    }
    if (t < L_){
        fwd_step(t, wqA, dmA0, dmA1);
    }

    // objective: ls + log(sum_n alpha)
    {
        float sq  = ((ac[0][0] + ac[0][1]) + (ac[1][0] + ac[1][1]))
                  + ((ac[2][0] + ac[2][1]) + (ac[3][0] + ac[3][1]));
        float sq8 = ((ac[0][2] + ac[0][3]) + (ac[1][2] + ac[1][3]))
                  + ((ac[2][2] + ac[2][3]) + (ac[3][2] + ac[3][3]));
        sq = qsum_(sq); sq8 = qsum_(sq8);
        if (c2 == 0){ sredF[q*4 + warp] = sq; sredF[(q+8)*4 + warp] = sq8; }
        __syncthreads();
        if (warp == 0 && c2 == 0){
            float s0 = red4sum(&sredF[q*4]);
            float s1 = red4sum(&sredF[(q+8)*4]);
            g_rowobj[b0 + q]     = ls0 + logf(s0);
            g_rowobj[b0 + q + 8] = ls1 + logf(s1);
        }
    }
}

// deterministic final reduction
__global__ void finalize_kernel(float* __restrict__ out, int out_size){
    __shared__ float sred[512];
    int t = threadIdx.x;
    sred[t] = g_rowobj[t];
    __syncthreads();
    for (int o = 256; o > 0; o >>= 1){
        if (t < o) sred[t] += sred[t+o];
        __syncthreads();
    }
    for (int i = t; i < out_size; i += 512){
        out[i] = (i == 0) ? sred[0] : 0.0f;
    }
}

// ============================ launch ============================

extern "C" void kernel_launch(void* const* d_in, const int* in_sizes, int n_in,
                              void* d_out, int out_size){
    const float* sents   = (const float*)d_in[0];  // (L,B,D)
    const float* masks   = (const float*)d_in[1];  // (L,B)
    const float* tparams = (const float*)d_in[2];  // (S,S)
    const float* means   = (const float*)d_in[3];  // (S,D)
    const float* var     = (const float*)d_in[4];  // (D,)

    prep_var_kernel<<<1, 512>>>(var);
    prep_AW_kernel<<<256, 128>>>(tparams, means);
    gemm_kernel<<<NROWS/128, 256>>>(sents);
    forward_kernel<<<B_/16, 128>>>(masks);
    finalize_kernel<<<1, 512>>>((float*)d_out, out_size);
}